// round 2
// baseline (speedup 1.0000x reference)
#include <cuda_runtime.h>
#include <cuda_bf16.h>
#include <math.h>

#define D_MODEL 1024
#define D_FF    4096
#define NEXP    8
#define MAXK    4
#define MAXT    8192
#define MAXSLOTS (MAXT*MAXK)

typedef unsigned long long ull;

// ---------------- static device scratch (no runtime allocation) ----------------
__device__ int   g_counts[NEXP];
__device__ int   g_cursor[NEXP];
__device__ int   g_offsets[NEXP];
__device__ int   g_slot2tok[MAXSLOTS];
__device__ int   g_tok2slot[MAXSLOTS];
__device__ float g_topw[MAXSLOTS];
__device__ int   g_topidx[MAXSLOTS];
__device__ float g_h[(size_t)MAXSLOTS * D_FF];     // 512 MB
__device__ float g_y[(size_t)MAXSLOTS * D_MODEL];  // 128 MB

// ---------------- packed f32x2 helpers (Blackwell FFMA2 path) ----------------
__device__ __forceinline__ void ffma2(ull& d, ull a, ull b) {
    asm("fma.rn.f32x2 %0, %1, %2, %0;" : "+l"(d) : "l"(a), "l"(b));
}
__device__ __forceinline__ ull bcast2(float v) {
    ull r; unsigned u = __float_as_uint(v);
    asm("mov.b64 %0, {%1, %1};" : "=l"(r) : "r"(u));
    return r;
}
__device__ __forceinline__ float2 unpack2(ull v) {
    unsigned lo, hi;
    asm("mov.b64 {%0, %1}, %2;" : "=r"(lo), "=r"(hi) : "l"(v));
    float2 f; f.x = __uint_as_float(lo); f.y = __uint_as_float(hi);
    return f;
}
__device__ __forceinline__ int clamp_k(const int* kptr) {
    int kk = 2;
    if (kptr) {
        kk = *kptr;
        kk = kk < 1 ? 1 : (kk > MAXK ? MAXK : kk);
    }
    return kk;
}

// ---------------- small kernels ----------------
__global__ void init_kernel() {
    if (threadIdx.x < NEXP) g_counts[threadIdx.x] = 0;
}

// One warp per token: logits (8 dots of length 1024), top-k, softmax over top-k.
__global__ void router_kernel(const float* __restrict__ x,
                              const float* __restrict__ gW,
                              const float* __restrict__ gb,
                              const int* kptr, int T) {
    int gw   = (blockIdx.x * blockDim.x + threadIdx.x) >> 5;
    int lane = threadIdx.x & 31;
    if (gw >= T) return;

    const float* xt = x + (size_t)gw * D_MODEL;
    float xr[32];
#pragma unroll
    for (int j = 0; j < 32; j++) xr[j] = xt[lane + j * 32];

    float lg[NEXP];
#pragma unroll
    for (int e = 0; e < NEXP; e++) {
        const float* w = gW + e * D_MODEL;
        float a = 0.f;
#pragma unroll
        for (int j = 0; j < 32; j++) a = fmaf(xr[j], w[lane + j * 32], a);
#pragma unroll
        for (int o = 16; o > 0; o >>= 1) a += __shfl_xor_sync(0xffffffffu, a, o);
        lg[e] = a + gb[e];
    }

    if (lane == 0) {
        int kk = clamp_k(kptr);
        float sc[MAXK]; int sel[MAXK];
        unsigned used = 0;
        for (int j = 0; j < kk; j++) {
            float bv = -3.0e38f; int bi = 0;
            for (int e = 0; e < NEXP; e++) {
                if (!((used >> e) & 1u) && lg[e] > bv) { bv = lg[e]; bi = e; }
            }
            used |= 1u << bi; sel[j] = bi; sc[j] = bv;
        }
        float m = sc[0], s = 0.f, p[MAXK];
        for (int j = 0; j < kk; j++) { p[j] = __expf(sc[j] - m); s += p[j]; }
        float inv = 1.f / s;
        for (int j = 0; j < kk; j++) {
            g_topidx[gw * MAXK + j] = sel[j];
            g_topw  [gw * MAXK + j] = p[j] * inv;
            atomicAdd(&g_counts[sel[j]], 1);
        }
    }
}

__global__ void offsets_kernel() {
    if (threadIdx.x == 0 && blockIdx.x == 0) {
        int off = 0;
        for (int e = 0; e < NEXP; e++) {
            g_offsets[e] = off;
            off += g_counts[e];
            g_cursor[e] = 0;
        }
    }
}

__global__ void assign_kernel(const int* kptr, int T) {
    int tid = blockIdx.x * blockDim.x + threadIdx.x;
    if (tid >= T * MAXK) return;
    int t = tid / MAXK, j = tid % MAXK;
    int kk = clamp_k(kptr);
    if (j >= kk) return;
    int e = g_topidx[t * MAXK + j];
    int r = atomicAdd(&g_cursor[e], 1);
    int slot = g_offsets[e] + r;
    g_slot2tok[slot] = t;
    g_tok2slot[t * MAXK + j] = slot;
}

// ---------------- GEMM1: h = silu(x Wg^T) * (x W1^T), gathered rows ----------------
// Tile: BM=128, BN=64, BK=16. 256 threads, per-thread 8x4 outputs for each of
// the two matrices, accumulated as packed f32x2 (FFMA2).
__global__ __launch_bounds__(256) void gemm1_kernel(
    const float* __restrict__ x,
    const float* __restrict__ Wg,
    const float* __restrict__ W1) {
    const int e   = blockIdx.z;
    const int cnt = g_counts[e];
    const int m0  = blockIdx.x * 128;
    if (m0 >= cnt) return;
    const int n0   = blockIdx.y * 64;
    const int offs = g_offsets[e];

    __shared__ float As[16][132];
    __shared__ float Bg[16][68];
    __shared__ float Bv[16][68];
    __shared__ int   stok[128];

    const int tid = threadIdx.x;
    const int tx  = tid & 15;
    const int ty  = tid >> 4;

    if (tid < 128) {
        int r = m0 + tid;
        stok[tid] = (r < cnt) ? g_slot2tok[offs + r] : 0;
    }
    __syncthreads();

    const float* wg = Wg + (size_t)e * D_FF * D_MODEL;
    const float* w1 = W1 + (size_t)e * D_FF * D_MODEL;

    ull accg[8][2], accv[8][2];
#pragma unroll
    for (int i = 0; i < 8; i++) {
        accg[i][0] = 0ULL; accg[i][1] = 0ULL;
        accv[i][0] = 0ULL; accv[i][1] = 0ULL;
    }

    const int lrow = tid >> 2;          // 0..63
    const int lc4  = (tid & 3) * 4;     // 0,4,8,12

    for (int k0 = 0; k0 < D_MODEL; k0 += 16) {
        // A tile: 128 rows x 16 k (gathered, stored k-major in smem)
#pragma unroll
        for (int l = 0; l < 2; l++) {
            int row = lrow + l * 64;
            float4 v = *reinterpret_cast<const float4*>(
                &x[(size_t)stok[row] * D_MODEL + k0 + lc4]);
            As[lc4 + 0][row] = v.x; As[lc4 + 1][row] = v.y;
            As[lc4 + 2][row] = v.z; As[lc4 + 3][row] = v.w;
        }
        // B tiles: 64 rows x 16 k each (Wg and W1 are [D_FF, D] row-major)
        {
            float4 vg = *reinterpret_cast<const float4*>(
                &wg[(size_t)(n0 + lrow) * D_MODEL + k0 + lc4]);
            Bg[lc4 + 0][lrow] = vg.x; Bg[lc4 + 1][lrow] = vg.y;
            Bg[lc4 + 2][lrow] = vg.z; Bg[lc4 + 3][lrow] = vg.w;
            float4 vv = *reinterpret_cast<const float4*>(
                &w1[(size_t)(n0 + lrow) * D_MODEL + k0 + lc4]);
            Bv[lc4 + 0][lrow] = vv.x; Bv[lc4 + 1][lrow] = vv.y;
            Bv[lc4 + 2][lrow] = vv.z; Bv[lc4 + 3][lrow] = vv.w;
        }
        __syncthreads();
#pragma unroll
        for (int kk = 0; kk < 16; kk++) {
            float4 a0 = *reinterpret_cast<const float4*>(&As[kk][ty * 8]);
            float4 a1 = *reinterpret_cast<const float4*>(&As[kk][ty * 8 + 4]);
            const ull* bgp = reinterpret_cast<const ull*>(&Bg[kk][tx * 4]);
            ull bg0 = bgp[0], bg1 = bgp[1];
            const ull* bvp = reinterpret_cast<const ull*>(&Bv[kk][tx * 4]);
            ull bv0 = bvp[0], bv1 = bvp[1];
            float am[8] = {a0.x, a0.y, a0.z, a0.w, a1.x, a1.y, a1.z, a1.w};
#pragma unroll
            for (int i = 0; i < 8; i++) {
                ull a2 = bcast2(am[i]);
                ffma2(accg[i][0], a2, bg0);
                ffma2(accg[i][1], a2, bg1);
                ffma2(accv[i][0], a2, bv0);
                ffma2(accv[i][1], a2, bv1);
            }
        }
        __syncthreads();
    }

    // epilogue: h = silu(g) * v
#pragma unroll
    for (int i = 0; i < 8; i++) {
        int r = m0 + ty * 8 + i;
        if (r < cnt) {
            float2 g0 = unpack2(accg[i][0]);
            float2 g1 = unpack2(accg[i][1]);
            float2 v0 = unpack2(accv[i][0]);
            float2 v1 = unpack2(accv[i][1]);
            float4 o;
            o.x = g0.x / (1.f + __expf(-g0.x)) * v0.x;
            o.y = g0.y / (1.f + __expf(-g0.y)) * v0.y;
            o.z = g1.x / (1.f + __expf(-g1.x)) * v1.x;
            o.w = g1.y / (1.f + __expf(-g1.y)) * v1.y;
            *reinterpret_cast<float4*>(
                &g_h[(size_t)(offs + r) * D_FF + n0 + tx * 4]) = o;
        }
    }
}

// ---------------- GEMM2: y = h W2^T ----------------
__global__ __launch_bounds__(256) void gemm2_kernel(const float* __restrict__ W2) {
    const int e   = blockIdx.z;
    const int cnt = g_counts[e];
    const int m0  = blockIdx.x * 128;
    if (m0 >= cnt) return;
    const int n0   = blockIdx.y * 64;
    const int offs = g_offsets[e];

    __shared__ float As[16][132];
    __shared__ float Bs[16][68];

    const int tid = threadIdx.x;
    const int tx  = tid & 15;
    const int ty  = tid >> 4;
    const float* w2 = W2 + (size_t)e * D_MODEL * D_FF;

    ull acc[8][2];
#pragma unroll
    for (int i = 0; i < 8; i++) { acc[i][0] = 0ULL; acc[i][1] = 0ULL; }

    const int lrow = tid >> 2;
    const int lc4  = (tid & 3) * 4;

    for (int k0 = 0; k0 < D_FF; k0 += 16) {
#pragma unroll
        for (int l = 0; l < 2; l++) {
            int row = lrow + l * 64;
            int rr  = m0 + row; if (rr >= cnt) rr = cnt - 1;  // stay in-bounds
            float4 v = *reinterpret_cast<const float4*>(
                &g_h[(size_t)(offs + rr) * D_FF + k0 + lc4]);
            As[lc4 + 0][row] = v.x; As[lc4 + 1][row] = v.y;
            As[lc4 + 2][row] = v.z; As[lc4 + 3][row] = v.w;
        }
        {
            float4 v = *reinterpret_cast<const float4*>(
                &w2[(size_t)(n0 + lrow) * D_FF + k0 + lc4]);
            Bs[lc4 + 0][lrow] = v.x; Bs[lc4 + 1][lrow] = v.y;
            Bs[lc4 + 2][lrow] = v.z; Bs[lc4 + 3][lrow] = v.w;
        }
        __syncthreads();
#pragma unroll
        for (int kk = 0; kk < 16; kk++) {
            float4 a0 = *reinterpret_cast<const float4*>(&As[kk][ty * 8]);
            float4 a1 = *reinterpret_cast<const float4*>(&As[kk][ty * 8 + 4]);
            const ull* bp = reinterpret_cast<const ull*>(&Bs[kk][tx * 4]);
            ull b0 = bp[0], b1 = bp[1];
            float am[8] = {a0.x, a0.y, a0.z, a0.w, a1.x, a1.y, a1.z, a1.w};
#pragma unroll
            for (int i = 0; i < 8; i++) {
                ull a2 = bcast2(am[i]);
                ffma2(acc[i][0], a2, b0);
                ffma2(acc[i][1], a2, b1);
            }
        }
        __syncthreads();
    }

#pragma unroll
    for (int i = 0; i < 8; i++) {
        int r = m0 + ty * 8 + i;
        if (r < cnt) {
            float2 c0 = unpack2(acc[i][0]);
            float2 c1 = unpack2(acc[i][1]);
            float4 o; o.x = c0.x; o.y = c0.y; o.z = c1.x; o.w = c1.y;
            *reinterpret_cast<float4*>(
                &g_y[(size_t)(offs + r) * D_MODEL + n0 + tx * 4]) = o;
        }
    }
}

// ---------------- combine: out[t] = sum_j w_j * y[slot(t,j)] ----------------
__global__ void combine_kernel(const int* kptr, float* __restrict__ out, int T) {
    int tid = blockIdx.x * blockDim.x + threadIdx.x;
    int total = T * (D_MODEL / 4);
    if (tid >= total) return;
    int t = tid / (D_MODEL / 4);
    int c = tid % (D_MODEL / 4);
    int kk = clamp_k(kptr);
    float4 o = make_float4(0.f, 0.f, 0.f, 0.f);
    for (int j = 0; j < kk; j++) {
        int slot = g_tok2slot[t * MAXK + j];
        float w  = g_topw[t * MAXK + j];
        float4 yv = *reinterpret_cast<const float4*>(
            &g_y[(size_t)slot * D_MODEL + c * 4]);
        o.x += w * yv.x; o.y += w * yv.y; o.z += w * yv.z; o.w += w * yv.w;
    }
    *reinterpret_cast<float4*>(&out[(size_t)t * D_MODEL + c * 4]) = o;
}

// ---------------- launch ----------------
extern "C" void kernel_launch(void* const* d_in, const int* in_sizes, int n_in,
                              void* d_out, int out_size) {
    const float* x  = (const float*)d_in[0];
    const float* gW = (const float*)d_in[1];
    const float* gb = (const float*)d_in[2];
    const float* Wg = (const float*)d_in[3];
    const float* W1 = (const float*)d_in[4];
    const float* W2 = (const float*)d_in[5];
    const int* kptr = (n_in > 6) ? (const int*)d_in[6] : nullptr;
    float* out = (float*)d_out;
    const int T = in_sizes[0] / D_MODEL;  // 8192

    init_kernel<<<1, 32>>>();
    router_kernel<<<(T + 7) / 8, 256>>>(x, gW, gb, kptr, T);
    offsets_kernel<<<1, 1>>>();
    assign_kernel<<<(T * MAXK + 255) / 256, 256>>>(kptr, T);

    dim3 g1((T + 127) / 128, D_FF / 64, NEXP);
    gemm1_kernel<<<g1, 256>>>(x, Wg, W1);

    dim3 g2((T + 127) / 128, D_MODEL / 64, NEXP);
    gemm2_kernel<<<g2, 256>>>(W2);

    combine_kernel<<<(T * (D_MODEL / 4) + 255) / 256, 256>>>(kptr, out, T);
}

// round 6
// speedup vs baseline: 2.1162x; 2.1162x over previous
#include <cuda_runtime.h>
#include <cuda_bf16.h>
#include <math.h>
#include <stdint.h>

#define D_MODEL 1024
#define D_FF    4096
#define NEXP    8
#define MAXK    4
#define MAXT    8192
#define MAXSLOTS (MAXT*MAXK)
#define PADS     (MAXSLOTS+256)

typedef unsigned long long ull;

// ---------------- static device scratch ----------------
__device__ int   g_counts[NEXP];
__device__ int   g_cursor[NEXP];
__device__ int   g_offsets[NEXP];
__device__ int   g_slot2tok[MAXSLOTS];
__device__ int   g_tok2slot[MAXSLOTS];
__device__ float g_topw[MAXSLOTS];
__device__ int   g_topidx[MAXSLOTS];

__device__ __align__(256) __nv_bfloat16 g_wghi[(size_t)NEXP*D_FF*D_MODEL];
__device__ __align__(256) __nv_bfloat16 g_wglo[(size_t)NEXP*D_FF*D_MODEL];
__device__ __align__(256) __nv_bfloat16 g_w1hi[(size_t)NEXP*D_FF*D_MODEL];
__device__ __align__(256) __nv_bfloat16 g_w1lo[(size_t)NEXP*D_FF*D_MODEL];
__device__ __align__(256) __nv_bfloat16 g_w2hi[(size_t)NEXP*D_MODEL*D_FF];
__device__ __align__(256) __nv_bfloat16 g_w2lo[(size_t)NEXP*D_MODEL*D_FF];
__device__ __align__(256) __nv_bfloat16 g_ahi[(size_t)PADS*D_MODEL];
__device__ __align__(256) __nv_bfloat16 g_alo[(size_t)PADS*D_MODEL];
__device__ __align__(256) __nv_bfloat16 g_hhi[(size_t)PADS*D_FF];
__device__ __align__(256) __nv_bfloat16 g_hlo[(size_t)PADS*D_FF];
__device__ __align__(256) float         g_y[(size_t)MAXSLOTS*D_MODEL];

// ---------------- helpers ----------------
__device__ __forceinline__ uint32_t s2u(const void* p) {
    uint32_t a;
    asm("{ .reg .u64 t; cvta.to.shared.u64 t, %1; cvt.u32.u64 %0, t; }"
        : "=r"(a) : "l"(p));
    return a;
}
__device__ __forceinline__ void cpasync16(uint32_t dst, const void* src) {
    asm volatile("cp.async.cg.shared.global [%0], [%1], 16;" :: "r"(dst), "l"(src) : "memory");
}
#define CP_COMMIT() asm volatile("cp.async.commit_group;" ::: "memory")
#define CP_WAIT1()  asm volatile("cp.async.wait_group 1;" ::: "memory")

__device__ __forceinline__ void ldsm4(uint32_t (&r)[4], uint32_t addr) {
    asm volatile("ldmatrix.sync.aligned.m8n8.x4.shared.b16 {%0,%1,%2,%3}, [%4];"
                 : "=r"(r[0]), "=r"(r[1]), "=r"(r[2]), "=r"(r[3]) : "r"(addr));
}
__device__ __forceinline__ void mma16816(float (&c)[4], const uint32_t (&a)[4],
                                         uint32_t b0, uint32_t b1) {
    asm volatile(
        "mma.sync.aligned.m16n8k16.row.col.f32.bf16.bf16.f32 "
        "{%0,%1,%2,%3}, {%4,%5,%6,%7}, {%8,%9}, {%0,%1,%2,%3};"
        : "+f"(c[0]), "+f"(c[1]), "+f"(c[2]), "+f"(c[3])
        : "r"(a[0]), "r"(a[1]), "r"(a[2]), "r"(a[3]), "r"(b0), "r"(b1));
}

union UB2 { __nv_bfloat162 b; uint32_t u; };
__device__ __forceinline__ uint32_t pack_split(float a, float b, uint32_t& lo) {
    UB2 h; h.b = __floats2bfloat162_rn(a, b);
    float ra = a - __low2float(h.b);
    float rb = b - __high2float(h.b);
    UB2 l; l.b = __floats2bfloat162_rn(ra, rb);
    lo = l.u;
    return h.u;
}
__device__ __forceinline__ int clamp_k(const int* kptr) {
    int kk = 2;
    if (kptr) { kk = *kptr; kk = kk < 1 ? 1 : (kk > MAXK ? MAXK : kk); }
    return kk;
}

// ---------------- routing kernels ----------------
__global__ void init_kernel() {
    if (threadIdx.x < NEXP) g_counts[threadIdx.x] = 0;
}

__global__ void router_kernel(const float* __restrict__ x,
                              const float* __restrict__ gW,
                              const float* __restrict__ gb,
                              const int* kptr, int T) {
    int gw = (blockIdx.x * blockDim.x + threadIdx.x) >> 5;
    int lane = threadIdx.x & 31;
    if (gw >= T) return;
    const float* xt = x + (size_t)gw * D_MODEL;
    float xr[32];
#pragma unroll
    for (int j = 0; j < 32; j++) xr[j] = xt[lane + j * 32];
    float lg[NEXP];
#pragma unroll
    for (int e = 0; e < NEXP; e++) {
        const float* w = gW + e * D_MODEL;
        float a = 0.f;
#pragma unroll
        for (int j = 0; j < 32; j++) a = fmaf(xr[j], w[lane + j * 32], a);
#pragma unroll
        for (int o = 16; o > 0; o >>= 1) a += __shfl_xor_sync(0xffffffffu, a, o);
        lg[e] = a + gb[e];
    }
    if (lane == 0) {
        int kk = clamp_k(kptr);
        float sc[MAXK]; int sel[MAXK];
        unsigned used = 0;
        for (int j = 0; j < kk; j++) {
            float bv = -3.0e38f; int bi = 0;
            for (int e = 0; e < NEXP; e++)
                if (!((used >> e) & 1u) && lg[e] > bv) { bv = lg[e]; bi = e; }
            used |= 1u << bi; sel[j] = bi; sc[j] = bv;
        }
        float m = sc[0], s = 0.f, p[MAXK];
        for (int j = 0; j < kk; j++) { p[j] = __expf(sc[j] - m); s += p[j]; }
        float inv = 1.f / s;
        for (int j = 0; j < kk; j++) {
            g_topidx[gw * MAXK + j] = sel[j];
            g_topw[gw * MAXK + j] = p[j] * inv;
            atomicAdd(&g_counts[sel[j]], 1);
        }
    }
}

__global__ void offsets_kernel() {
    if (threadIdx.x == 0 && blockIdx.x == 0) {
        int off = 0;
        for (int e = 0; e < NEXP; e++) { g_offsets[e] = off; off += g_counts[e]; g_cursor[e] = 0; }
    }
}

__global__ void assign_kernel(const int* kptr, int T) {
    int tid = blockIdx.x * blockDim.x + threadIdx.x;
    if (tid >= T * MAXK) return;
    int t = tid / MAXK, j = tid % MAXK;
    int kk = clamp_k(kptr);
    if (j >= kk) return;
    int e = g_topidx[t * MAXK + j];
    int r = atomicAdd(&g_cursor[e], 1);
    int slot = g_offsets[e] + r;
    g_slot2tok[slot] = t;
    g_tok2slot[t * MAXK + j] = slot;
}

// ---------------- split kernels ----------------
__global__ void splitw_kernel(const float* __restrict__ src, int which, int n8) {
    __nv_bfloat16* hi = which == 0 ? g_wghi : which == 1 ? g_w1hi : g_w2hi;
    __nv_bfloat16* lo = which == 0 ? g_wglo : which == 1 ? g_w1lo : g_w2lo;
    for (int i = blockIdx.x * blockDim.x + threadIdx.x; i < n8; i += gridDim.x * blockDim.x) {
        const float4* s = (const float4*)src + (size_t)i * 2;
        float4 a = s[0], b = s[1];
        uint32_t l0, l1, l2, l3;
        uint32_t h0 = pack_split(a.x, a.y, l0);
        uint32_t h1 = pack_split(a.z, a.w, l1);
        uint32_t h2 = pack_split(b.x, b.y, l2);
        uint32_t h3 = pack_split(b.z, b.w, l3);
        ((uint4*)hi)[i] = make_uint4(h0, h1, h2, h3);
        ((uint4*)lo)[i] = make_uint4(l0, l1, l2, l3);
    }
}

__global__ void splitx_kernel(const float* __restrict__ x) {
    int slot = blockIdx.x;
    int total = g_offsets[NEXP - 1] + g_counts[NEXP - 1];
    if (slot >= total) return;
    int tok = g_slot2tok[slot];
    int t = threadIdx.x;
    const float4* s = (const float4*)(x + (size_t)tok * D_MODEL) + t * 2;
    float4 a = s[0], b = s[1];
    uint32_t l0, l1, l2, l3;
    uint32_t h0 = pack_split(a.x, a.y, l0);
    uint32_t h1 = pack_split(a.z, a.w, l1);
    uint32_t h2 = pack_split(b.x, b.y, l2);
    uint32_t h3 = pack_split(b.z, b.w, l3);
    ((uint4*)(g_ahi + (size_t)slot * D_MODEL))[t] = make_uint4(h0, h1, h2, h3);
    ((uint4*)(g_alo + (size_t)slot * D_MODEL))[t] = make_uint4(l0, l1, l2, l3);
}

// ---------------- GEMM tiling constants ----------------
// smem row pitch: 32 bf16 data + 8 pad = 40 bf16 = 80 bytes (ldmatrix conflict-free)
#define STAGE 61440

// GEMM1 stage: A_hi[128x32]@0, A_lo@10240, B_hi[256x32]@20480, B_lo@40960
__device__ __forceinline__ void g1_load(
    uint32_t base,
    const __nv_bfloat16* aHi, const __nv_bfloat16* aLo,
    const __nv_bfloat16* bgHi, const __nv_bfloat16* bgLo,
    const __nv_bfloat16* bvHi, const __nv_bfloat16* bvLo,
    int k0, int tid) {
#pragma unroll
    for (int i = 0; i < 4; i++) {                 // A: 1024 chunks
        int idx = tid + i * 256;
        int src = idx >> 9, rem = idx & 511;
        int row = rem >> 2, c = rem & 3;
        const __nv_bfloat16* g = (src ? aLo : aHi) + (size_t)row * D_MODEL + k0 + c * 8;
        cpasync16(base + src * 10240 + row * 80 + c * 16, g);
    }
#pragma unroll
    for (int i = 0; i < 8; i++) {                 // B: 2048 chunks
        int idx = tid + i * 256;
        int src = idx >> 10, rem = idx & 1023;
        int row = rem >> 2, c = rem & 3;
        const __nv_bfloat16* g;
        if (row < 128) g = (src ? bgLo : bgHi) + (size_t)row * D_MODEL + k0 + c * 8;
        else           g = (src ? bvLo : bvHi) + (size_t)(row - 128) * D_MODEL + k0 + c * 8;
        cpasync16(base + 20480 + src * 20480 + row * 80 + c * 16, g);
    }
}

// ---------------- GEMM1: G = X Wg^T, V = X W1^T, h = silu(G)*V ----------------
__global__ __launch_bounds__(256, 1) void gemm1_mma() {
    const int e = blockIdx.z;
    const int cnt = g_counts[e];
    const int m0 = blockIdx.x * 128;
    if (m0 >= cnt) return;
    const int n0 = blockIdx.y * 128;
    const int offs = g_offsets[e];
    extern __shared__ char smem[];
    uint32_t sb = s2u(smem);
    const int tid = threadIdx.x, lane = tid & 31, wid = tid >> 5;
    const int wM = wid >> 1, wN = wid & 1;

    const __nv_bfloat16* aHi = g_ahi + (size_t)(offs + m0) * D_MODEL;
    const __nv_bfloat16* aLo = g_alo + (size_t)(offs + m0) * D_MODEL;
    const size_t wb = (size_t)e * D_FF * D_MODEL + (size_t)n0 * D_MODEL;
    const __nv_bfloat16* bgHi = g_wghi + wb;
    const __nv_bfloat16* bgLo = g_wglo + wb;
    const __nv_bfloat16* bvHi = g_w1hi + wb;
    const __nv_bfloat16* bvLo = g_w1lo + wb;

    g1_load(sb, aHi, aLo, bgHi, bgLo, bvHi, bvLo, 0, tid);  CP_COMMIT();
    g1_load(sb + STAGE, aHi, aLo, bgHi, bgLo, bvHi, bvLo, 32, tid);  CP_COMMIT();

    float accG[2][8][4] = {}, accV[2][8][4] = {};
    const int aRow = lane & 15, aK = (lane >> 4) << 3;
    const int bRow = (lane & 7) | ((lane >> 4) << 3);
    const int bK = ((lane >> 3) & 1) << 3;

    for (int j = 0; j < 32; j++) {
        const int buf = j & 1;
        CP_WAIT1();
        __syncthreads();
        const uint32_t bA = sb + buf * STAGE;
#pragma unroll
        for (int kk = 0; kk < 32; kk += 16) {
            uint32_t ah[2][4], al[2][4];
#pragma unroll
            for (int mt = 0; mt < 2; mt++) {
                uint32_t r = wM * 32 + mt * 16 + aRow;
                uint32_t c2 = (kk + aK) * 2;
                ldsm4(ah[mt], bA + r * 80 + c2);
                ldsm4(al[mt], bA + 10240 + r * 80 + c2);
            }
#pragma unroll
            for (int np = 0; np < 4; np++) {
                uint32_t rG = wN * 64 + np * 16 + bRow;
                uint32_t cb2 = (kk + bK) * 2;
                uint32_t bh[4], bl[4];
                ldsm4(bh, bA + 20480 + rG * 80 + cb2);
                ldsm4(bl, bA + 40960 + rG * 80 + cb2);
#pragma unroll
                for (int mt = 0; mt < 2; mt++)
#pragma unroll
                    for (int sub = 0; sub < 2; sub++) {
                        mma16816(accG[mt][np * 2 + sub], ah[mt], bh[sub * 2], bh[sub * 2 + 1]);
                        mma16816(accG[mt][np * 2 + sub], ah[mt], bl[sub * 2], bl[sub * 2 + 1]);
                        mma16816(accG[mt][np * 2 + sub], al[mt], bh[sub * 2], bh[sub * 2 + 1]);
                    }
                uint32_t rV = 128 + rG;
                ldsm4(bh, bA + 20480 + rV * 80 + cb2);
                ldsm4(bl, bA + 40960 + rV * 80 + cb2);
#pragma unroll
                for (int mt = 0; mt < 2; mt++)
#pragma unroll
                    for (int sub = 0; sub < 2; sub++) {
                        mma16816(accV[mt][np * 2 + sub], ah[mt], bh[sub * 2], bh[sub * 2 + 1]);
                        mma16816(accV[mt][np * 2 + sub], ah[mt], bl[sub * 2], bl[sub * 2 + 1]);
                        mma16816(accV[mt][np * 2 + sub], al[mt], bh[sub * 2], bh[sub * 2 + 1]);
                    }
            }
        }
        __syncthreads();
        if (j + 2 < 32)
            g1_load(sb + buf * STAGE, aHi, aLo, bgHi, bgLo, bvHi, bvLo, (j + 2) * 32, tid);
        CP_COMMIT();
    }

#pragma unroll
    for (int mt = 0; mt < 2; mt++)
#pragma unroll
        for (int half = 0; half < 2; half++) {
            int r = m0 + wM * 32 + mt * 16 + (lane >> 2) + half * 8;
            if (r < cnt) {
                size_t rowb = (size_t)(offs + r) * D_FF;
#pragma unroll
                for (int nt = 0; nt < 8; nt++) {
                    float gg0 = accG[mt][nt][half * 2 + 0];
                    float gg1 = accG[mt][nt][half * 2 + 1];
                    float vv0 = accV[mt][nt][half * 2 + 0];
                    float vv1 = accV[mt][nt][half * 2 + 1];
                    float h0 = gg0 / (1.f + __expf(-gg0)) * vv0;
                    float h1 = gg1 / (1.f + __expf(-gg1)) * vv1;
                    uint32_t lo, hi = pack_split(h0, h1, lo);
                    int col = n0 + wN * 64 + nt * 8 + (lane & 3) * 2;
                    *(uint32_t*)(g_hhi + rowb + col) = hi;
                    *(uint32_t*)(g_hlo + rowb + col) = lo;
                }
            }
        }
}

// GEMM2 stage: A_hi[256x32]@0, A_lo@20480, B_hi[128x32]@40960, B_lo@51200
__device__ __forceinline__ void g2_load(
    uint32_t base,
    const __nv_bfloat16* aHi, const __nv_bfloat16* aLo,
    const __nv_bfloat16* bHi, const __nv_bfloat16* bLo,
    int k0, int tid) {
#pragma unroll
    for (int i = 0; i < 8; i++) {                 // A: 2048 chunks
        int idx = tid + i * 256;
        int src = idx >> 10, rem = idx & 1023;
        int row = rem >> 2, c = rem & 3;
        const __nv_bfloat16* g = (src ? aLo : aHi) + (size_t)row * D_FF + k0 + c * 8;
        cpasync16(base + src * 20480 + row * 80 + c * 16, g);
    }
#pragma unroll
    for (int i = 0; i < 4; i++) {                 // B: 1024 chunks
        int idx = tid + i * 256;
        int src = idx >> 9, rem = idx & 511;
        int row = rem >> 2, c = rem & 3;
        const __nv_bfloat16* g = (src ? bLo : bHi) + (size_t)row * D_FF + k0 + c * 8;
        cpasync16(base + 40960 + src * 10240 + row * 80 + c * 16, g);
    }
}

// ---------------- GEMM2: y = h W2^T ----------------
__global__ __launch_bounds__(256, 1) void gemm2_mma() {
    const int e = blockIdx.z;
    const int cnt = g_counts[e];
    const int m0 = blockIdx.x * 256;
    if (m0 >= cnt) return;
    const int n0 = blockIdx.y * 128;
    const int offs = g_offsets[e];
    extern __shared__ char smem[];
    uint32_t sb = s2u(smem);
    const int tid = threadIdx.x, lane = tid & 31, wid = tid >> 5;
    const int wM = wid >> 1, wN = wid & 1;

    const __nv_bfloat16* aHi = g_hhi + (size_t)(offs + m0) * D_FF;
    const __nv_bfloat16* aLo = g_hlo + (size_t)(offs + m0) * D_FF;
    const size_t wb = (size_t)e * D_MODEL * D_FF + (size_t)n0 * D_FF;
    const __nv_bfloat16* bHi = g_w2hi + wb;
    const __nv_bfloat16* bLo = g_w2lo + wb;

    g2_load(sb, aHi, aLo, bHi, bLo, 0, tid);  CP_COMMIT();
    g2_load(sb + STAGE, aHi, aLo, bHi, bLo, 32, tid);  CP_COMMIT();

    float acc[4][8][4] = {};
    const int aRow = lane & 15, aK = (lane >> 4) << 3;
    const int bRow = (lane & 7) | ((lane >> 4) << 3);
    const int bK = ((lane >> 3) & 1) << 3;

    for (int j = 0; j < 128; j++) {
        const int buf = j & 1;
        CP_WAIT1();
        __syncthreads();
        const uint32_t bA = sb + buf * STAGE;
#pragma unroll
        for (int kk = 0; kk < 32; kk += 16) {
            uint32_t ah[4][4], al[4][4];
#pragma unroll
            for (int mt = 0; mt < 4; mt++) {
                uint32_t r = wM * 64 + mt * 16 + aRow;
                uint32_t c2 = (kk + aK) * 2;
                ldsm4(ah[mt], bA + r * 80 + c2);
                ldsm4(al[mt], bA + 20480 + r * 80 + c2);
            }
#pragma unroll
            for (int np = 0; np < 4; np++) {
                uint32_t rB = wN * 64 + np * 16 + bRow;
                uint32_t cb2 = (kk + bK) * 2;
                uint32_t bh[4], bl[4];
                ldsm4(bh, bA + 40960 + rB * 80 + cb2);
                ldsm4(bl, bA + 51200 + rB * 80 + cb2);
#pragma unroll
                for (int mt = 0; mt < 4; mt++)
#pragma unroll
                    for (int sub = 0; sub < 2; sub++) {
                        mma16816(acc[mt][np * 2 + sub], ah[mt], bh[sub * 2], bh[sub * 2 + 1]);
                        mma16816(acc[mt][np * 2 + sub], ah[mt], bl[sub * 2], bl[sub * 2 + 1]);
                        mma16816(acc[mt][np * 2 + sub], al[mt], bh[sub * 2], bh[sub * 2 + 1]);
                    }
            }
        }
        __syncthreads();
        if (j + 2 < 128)
            g2_load(sb + buf * STAGE, aHi, aLo, bHi, bLo, (j + 2) * 32, tid);
        CP_COMMIT();
    }

#pragma unroll
    for (int mt = 0; mt < 4; mt++)
#pragma unroll
        for (int half = 0; half < 2; half++) {
            int r = m0 + wM * 64 + mt * 16 + (lane >> 2) + half * 8;
            if (r < cnt) {
                size_t rowb = (size_t)(offs + r) * D_MODEL;
#pragma unroll
                for (int nt = 0; nt < 8; nt++) {
                    int col = n0 + wN * 64 + nt * 8 + (lane & 3) * 2;
                    float2 o;
                    o.x = acc[mt][nt][half * 2 + 0];
                    o.y = acc[mt][nt][half * 2 + 1];
                    *(float2*)(g_y + rowb + col) = o;
                }
            }
        }
}

// ---------------- combine ----------------
__global__ void combine_kernel(const int* kptr, float* __restrict__ out, int T) {
    int tid = blockIdx.x * blockDim.x + threadIdx.x;
    int total = T * (D_MODEL / 4);
    if (tid >= total) return;
    int t = tid / (D_MODEL / 4);
    int c = tid % (D_MODEL / 4);
    int kk = clamp_k(kptr);
    float4 o = make_float4(0.f, 0.f, 0.f, 0.f);
    for (int j = 0; j < kk; j++) {
        int slot = g_tok2slot[t * MAXK + j];
        float w = g_topw[t * MAXK + j];
        float4 yv = *reinterpret_cast<const float4*>(&g_y[(size_t)slot * D_MODEL + c * 4]);
        o.x += w * yv.x; o.y += w * yv.y; o.z += w * yv.z; o.w += w * yv.w;
    }
    *reinterpret_cast<float4*>(&out[(size_t)t * D_MODEL + c * 4]) = o;
}

// ---------------- launch ----------------
extern "C" void kernel_launch(void* const* d_in, const int* in_sizes, int n_in,
                              void* d_out, int out_size) {
    const float* x  = (const float*)d_in[0];
    const float* gW = (const float*)d_in[1];
    const float* gb = (const float*)d_in[2];
    const float* Wg = (const float*)d_in[3];
    const float* W1 = (const float*)d_in[4];
    const float* W2 = (const float*)d_in[5];
    const int* kptr = (n_in > 6) ? (const int*)d_in[6] : nullptr;
    float* out = (float*)d_out;
    const int T = in_sizes[0] / D_MODEL;

    const int SMEM_TOT = 2 * STAGE;  // 122880
    cudaFuncSetAttribute(gemm1_mma, cudaFuncAttributeMaxDynamicSharedMemorySize, SMEM_TOT);
    cudaFuncSetAttribute(gemm2_mma, cudaFuncAttributeMaxDynamicSharedMemorySize, SMEM_TOT);

    init_kernel<<<1, 32>>>();
    router_kernel<<<(T + 7) / 8, 256>>>(x, gW, gb, kptr, T);
    offsets_kernel<<<1, 1>>>();
    assign_kernel<<<(T * MAXK + 255) / 256, 256>>>(kptr, T);
    splitx_kernel<<<T * MAXK, 128>>>(x);

    const int n8 = NEXP * D_FF * D_MODEL / 8;
    splitw_kernel<<<4096, 256>>>(Wg, 0, n8);
    splitw_kernel<<<4096, 256>>>(W1, 1, n8);
    splitw_kernel<<<4096, 256>>>(W2, 2, n8);

    gemm1_mma<<<dim3(T / 128, D_FF / 128, NEXP), 256, SMEM_TOT>>>();
    gemm2_mma<<<dim3(T / 256, D_MODEL / 128, NEXP), 256, SMEM_TOT>>>();

    combine_kernel<<<(T * (D_MODEL / 4) + 255) / 256, 256>>>(kptr, out, T);
}

// round 7
// speedup vs baseline: 2.7078x; 1.2795x over previous
#include <cuda_runtime.h>
#include <cuda_bf16.h>
#include <cuda_fp16.h>
#include <math.h>
#include <stdint.h>

#define D_MODEL 1024
#define D_FF    4096
#define NEXP    8
#define MAXK    4
#define MAXT    8192
#define MAXSLOTS (MAXT*MAXK)
#define PADS     (MAXSLOTS+256)

typedef unsigned long long ull;

// ---------------- static device scratch ----------------
__device__ int   g_counts[NEXP];
__device__ int   g_cursor[NEXP];
__device__ int   g_offsets[NEXP];
__device__ int   g_slot2tok[MAXSLOTS];
__device__ int   g_tok2slot[MAXSLOTS];
__device__ float g_topw[MAXSLOTS];
__device__ int   g_topidx[MAXSLOTS];

__device__ __align__(256) __half g_wghi[(size_t)NEXP*D_FF*D_MODEL];
__device__ __align__(256) __half g_w1hi[(size_t)NEXP*D_FF*D_MODEL];
__device__ __align__(256) __half g_w2hi[(size_t)NEXP*D_MODEL*D_FF];
__device__ __align__(256) __half g_w2lo[(size_t)NEXP*D_MODEL*D_FF];
__device__ __align__(256) __half g_ahi[(size_t)PADS*D_MODEL];
__device__ __align__(256) __half g_alo[(size_t)PADS*D_MODEL];
__device__ __align__(256) __half g_hhi[(size_t)PADS*D_FF];
__device__ __align__(256) __half g_hlo[(size_t)PADS*D_FF];
__device__ __align__(256) float  g_y[(size_t)MAXSLOTS*D_MODEL];

// ---------------- helpers ----------------
__device__ __forceinline__ uint32_t s2u(const void* p) {
    uint32_t a;
    asm("{ .reg .u64 t; cvta.to.shared.u64 t, %1; cvt.u32.u64 %0, t; }"
        : "=r"(a) : "l"(p));
    return a;
}
__device__ __forceinline__ void cpasync16(uint32_t dst, const void* src) {
    asm volatile("cp.async.cg.shared.global [%0], [%1], 16;" :: "r"(dst), "l"(src) : "memory");
}
#define CP_COMMIT() asm volatile("cp.async.commit_group;" ::: "memory")
#define CP_WAIT1()  asm volatile("cp.async.wait_group 1;" ::: "memory")

__device__ __forceinline__ void ldsm4(uint32_t (&r)[4], uint32_t addr) {
    asm volatile("ldmatrix.sync.aligned.m8n8.x4.shared.b16 {%0,%1,%2,%3}, [%4];"
                 : "=r"(r[0]), "=r"(r[1]), "=r"(r[2]), "=r"(r[3]) : "r"(addr));
}
__device__ __forceinline__ void mma16816(float (&c)[4], const uint32_t (&a)[4],
                                         uint32_t b0, uint32_t b1) {
    asm volatile(
        "mma.sync.aligned.m16n8k16.row.col.f32.f16.f16.f32 "
        "{%0,%1,%2,%3}, {%4,%5,%6,%7}, {%8,%9}, {%0,%1,%2,%3};"
        : "+f"(c[0]), "+f"(c[1]), "+f"(c[2]), "+f"(c[3])
        : "r"(a[0]), "r"(a[1]), "r"(a[2]), "r"(a[3]), "r"(b0), "r"(b1));
}

union UH2 { __half2 h; uint32_t u; };
__device__ __forceinline__ uint32_t pack_h2(float a, float b) {
    UH2 v; v.h = __floats2half2_rn(a, b);
    return v.u;
}
__device__ __forceinline__ uint32_t pack_split_h(float a, float b, uint32_t& lo) {
    UH2 h; h.h = __floats2half2_rn(a, b);
    float ra = a - __low2float(h.h);
    float rb = b - __high2float(h.h);
    UH2 l; l.h = __floats2half2_rn(ra, rb);
    lo = l.u;
    return h.u;
}
__device__ __forceinline__ int clamp_k(const int* kptr) {
    int kk = 2;
    if (kptr) { kk = *kptr; kk = kk < 1 ? 1 : (kk > MAXK ? MAXK : kk); }
    return kk;
}

// ---------------- routing kernels ----------------
__global__ void init_kernel() {
    if (threadIdx.x < NEXP) g_counts[threadIdx.x] = 0;
}

__global__ void router_kernel(const float* __restrict__ x,
                              const float* __restrict__ gW,
                              const float* __restrict__ gb,
                              const int* kptr, int T) {
    int gw = (blockIdx.x * blockDim.x + threadIdx.x) >> 5;
    int lane = threadIdx.x & 31;
    if (gw >= T) return;
    const float* xt = x + (size_t)gw * D_MODEL;
    float xr[32];
#pragma unroll
    for (int j = 0; j < 32; j++) xr[j] = xt[lane + j * 32];
    float lg[NEXP];
#pragma unroll
    for (int e = 0; e < NEXP; e++) {
        const float* w = gW + e * D_MODEL;
        float a = 0.f;
#pragma unroll
        for (int j = 0; j < 32; j++) a = fmaf(xr[j], w[lane + j * 32], a);
#pragma unroll
        for (int o = 16; o > 0; o >>= 1) a += __shfl_xor_sync(0xffffffffu, a, o);
        lg[e] = a + gb[e];
    }
    if (lane == 0) {
        int kk = clamp_k(kptr);
        float sc[MAXK]; int sel[MAXK];
        unsigned used = 0;
        for (int j = 0; j < kk; j++) {
            float bv = -3.0e38f; int bi = 0;
            for (int e = 0; e < NEXP; e++)
                if (!((used >> e) & 1u) && lg[e] > bv) { bv = lg[e]; bi = e; }
            used |= 1u << bi; sel[j] = bi; sc[j] = bv;
        }
        float m = sc[0], s = 0.f, p[MAXK];
        for (int j = 0; j < kk; j++) { p[j] = __expf(sc[j] - m); s += p[j]; }
        float inv = 1.f / s;
        for (int j = 0; j < kk; j++) {
            g_topidx[gw * MAXK + j] = sel[j];
            g_topw[gw * MAXK + j] = p[j] * inv;
            atomicAdd(&g_counts[sel[j]], 1);
        }
    }
}

__global__ void offsets_kernel() {
    if (threadIdx.x == 0 && blockIdx.x == 0) {
        int off = 0;
        for (int e = 0; e < NEXP; e++) { g_offsets[e] = off; off += g_counts[e]; g_cursor[e] = 0; }
    }
}

__global__ void assign_kernel(const int* kptr, int T) {
    int tid = blockIdx.x * blockDim.x + threadIdx.x;
    if (tid >= T * MAXK) return;
    int t = tid / MAXK, j = tid % MAXK;
    int kk = clamp_k(kptr);
    if (j >= kk) return;
    int e = g_topidx[t * MAXK + j];
    int r = atomicAdd(&g_cursor[e], 1);
    int slot = g_offsets[e] + r;
    g_slot2tok[slot] = t;
    g_tok2slot[t * MAXK + j] = slot;
}

// ---------------- split kernels ----------------
// which: 0=Wg (hi only), 1=W1 (hi only), 2=W2 (hi+lo)
__global__ void splitw_kernel(const float* __restrict__ src, int which, int n8) {
    __half* hi = which == 0 ? g_wghi : which == 1 ? g_w1hi : g_w2hi;
    __half* lo = g_w2lo;
    bool dolo = (which == 2);
    for (int i = blockIdx.x * blockDim.x + threadIdx.x; i < n8; i += gridDim.x * blockDim.x) {
        const float4* s = (const float4*)src + (size_t)i * 2;
        float4 a = s[0], b = s[1];
        if (dolo) {
            uint32_t l0, l1, l2, l3;
            uint32_t h0 = pack_split_h(a.x, a.y, l0);
            uint32_t h1 = pack_split_h(a.z, a.w, l1);
            uint32_t h2 = pack_split_h(b.x, b.y, l2);
            uint32_t h3 = pack_split_h(b.z, b.w, l3);
            ((uint4*)hi)[i] = make_uint4(h0, h1, h2, h3);
            ((uint4*)lo)[i] = make_uint4(l0, l1, l2, l3);
        } else {
            ((uint4*)hi)[i] = make_uint4(pack_h2(a.x, a.y), pack_h2(a.z, a.w),
                                         pack_h2(b.x, b.y), pack_h2(b.z, b.w));
        }
    }
}

__global__ void splitx_kernel(const float* __restrict__ x) {
    int slot = blockIdx.x;
    int total = g_offsets[NEXP - 1] + g_counts[NEXP - 1];
    if (slot >= total) return;
    int tok = g_slot2tok[slot];
    int t = threadIdx.x;
    const float4* s = (const float4*)(x + (size_t)tok * D_MODEL) + t * 2;
    float4 a = s[0], b = s[1];
    uint32_t l0, l1, l2, l3;
    uint32_t h0 = pack_split_h(a.x, a.y, l0);
    uint32_t h1 = pack_split_h(a.z, a.w, l1);
    uint32_t h2 = pack_split_h(b.x, b.y, l2);
    uint32_t h3 = pack_split_h(b.z, b.w, l3);
    ((uint4*)(g_ahi + (size_t)slot * D_MODEL))[t] = make_uint4(h0, h1, h2, h3);
    ((uint4*)(g_alo + (size_t)slot * D_MODEL))[t] = make_uint4(l0, l1, l2, l3);
}

// ---------------- GEMM tiling ----------------
// smem row pitch = 80 bytes (32 fp16 + 8 pad), ldmatrix conflict-free (proven R6)
#define STAGE1 40960
#define STAGE2 61440

// GEMM1 stage: A_hi[128]@0, A_lo@10240, Bg_hi[128]@20480, Bv_hi[128]@30720
__device__ __forceinline__ void g1_load(
    uint32_t base,
    const __half* aHi, const __half* aLo,
    const __half* bg, const __half* bv,
    int k0, int tid) {
#pragma unroll
    for (int i = 0; i < 2; i++) {          // A: 1024 chunks of 16B
        int idx = tid + i * 512;
        int src = idx >> 9, rem = idx & 511;
        int row = rem >> 2, c = rem & 3;
        const __half* g = (src ? aLo : aHi) + (size_t)row * D_MODEL + k0 + c * 8;
        cpasync16(base + src * 10240 + row * 80 + c * 16, g);
    }
#pragma unroll
    for (int i = 0; i < 2; i++) {          // B: 1024 chunks
        int idx = tid + i * 512;
        int mat = idx >> 9, rem = idx & 511;
        int row = rem >> 2, c = rem & 3;
        const __half* g = (mat ? bv : bg) + (size_t)row * D_MODEL + k0 + c * 8;
        cpasync16(base + 20480 + mat * 10240 + row * 80 + c * 16, g);
    }
}

// ---------------- GEMM1: G = X Wg^T, V = X W1^T, h = silu(G)*V ----------------
// 2-term fp16: (Ahi + Alo) * Bhi. 512 threads, warp grid 4M x 4N, tile 128x128.
__global__ __launch_bounds__(512, 1) void gemm1_mma() {
    const int e = blockIdx.z;
    const int cnt = g_counts[e];
    const int m0 = blockIdx.x * 128;
    if (m0 >= cnt) return;
    const int n0 = blockIdx.y * 128;
    const int offs = g_offsets[e];
    extern __shared__ char smem[];
    uint32_t sb = s2u(smem);
    const int tid = threadIdx.x, lane = tid & 31, wid = tid >> 5;
    const int wM = wid >> 2, wN = wid & 3;

    const __half* aHi = g_ahi + (size_t)(offs + m0) * D_MODEL;
    const __half* aLo = g_alo + (size_t)(offs + m0) * D_MODEL;
    const size_t wb = (size_t)e * D_FF * D_MODEL + (size_t)n0 * D_MODEL;
    const __half* bg = g_wghi + wb;
    const __half* bv = g_w1hi + wb;

    g1_load(sb, aHi, aLo, bg, bv, 0, tid);   CP_COMMIT();
    g1_load(sb + STAGE1, aHi, aLo, bg, bv, 32, tid);  CP_COMMIT();

    float accG[2][4][4] = {}, accV[2][4][4] = {};
    const int aRow = lane & 15, aK = (lane >> 4) << 3;
    const int bRow = (lane & 7) | ((lane >> 4) << 3);
    const int bK = ((lane >> 3) & 1) << 3;

    const int NCH = D_MODEL / 32;  // 32
    for (int j = 0; j < NCH; j++) {
        const int buf = j % 3;
        CP_WAIT1();
        __syncthreads();
        if (j + 2 < NCH)
            g1_load(sb + ((j + 2) % 3) * STAGE1, aHi, aLo, bg, bv, (j + 2) * 32, tid);
        CP_COMMIT();
        const uint32_t bA = sb + buf * STAGE1;
#pragma unroll
        for (int kk = 0; kk < 32; kk += 16) {
            uint32_t ah[2][4], al[2][4];
#pragma unroll
            for (int mt = 0; mt < 2; mt++) {
                uint32_t r = wM * 32 + mt * 16 + aRow;
                uint32_t c2 = (kk + aK) * 2;
                ldsm4(ah[mt], bA + r * 80 + c2);
                ldsm4(al[mt], bA + 10240 + r * 80 + c2);
            }
#pragma unroll
            for (int np = 0; np < 2; np++) {
                uint32_t rN = wN * 32 + np * 16 + bRow;
                uint32_t cb2 = (kk + bK) * 2;
                uint32_t bgf[4], bvf[4];
                ldsm4(bgf, bA + 20480 + rN * 80 + cb2);
                ldsm4(bvf, bA + 30720 + rN * 80 + cb2);
#pragma unroll
                for (int mt = 0; mt < 2; mt++)
#pragma unroll
                    for (int sub = 0; sub < 2; sub++) {
                        mma16816(accG[mt][np * 2 + sub], ah[mt], bgf[sub * 2], bgf[sub * 2 + 1]);
                        mma16816(accG[mt][np * 2 + sub], al[mt], bgf[sub * 2], bgf[sub * 2 + 1]);
                        mma16816(accV[mt][np * 2 + sub], ah[mt], bvf[sub * 2], bvf[sub * 2 + 1]);
                        mma16816(accV[mt][np * 2 + sub], al[mt], bvf[sub * 2], bvf[sub * 2 + 1]);
                    }
            }
        }
    }

#pragma unroll
    for (int mt = 0; mt < 2; mt++)
#pragma unroll
        for (int half_ = 0; half_ < 2; half_++) {
            int r = m0 + wM * 32 + mt * 16 + (lane >> 2) + half_ * 8;
            if (r < cnt) {
                size_t rowb = (size_t)(offs + r) * D_FF;
#pragma unroll
                for (int nt = 0; nt < 4; nt++) {
                    float gg0 = accG[mt][nt][half_ * 2 + 0];
                    float gg1 = accG[mt][nt][half_ * 2 + 1];
                    float vv0 = accV[mt][nt][half_ * 2 + 0];
                    float vv1 = accV[mt][nt][half_ * 2 + 1];
                    float h0 = gg0 / (1.f + __expf(-gg0)) * vv0;
                    float h1 = gg1 / (1.f + __expf(-gg1)) * vv1;
                    uint32_t lo, hi = pack_split_h(h0, h1, lo);
                    int col = n0 + wN * 32 + nt * 8 + (lane & 3) * 2;
                    *(uint32_t*)(g_hhi + rowb + col) = hi;
                    *(uint32_t*)(g_hlo + rowb + col) = lo;
                }
            }
        }
}

// GEMM2 stage: A_hi[256]@0, A_lo@20480, B_hi[128]@40960, B_lo@51200
__device__ __forceinline__ void g2_load(
    uint32_t base,
    const __half* aHi, const __half* aLo,
    const __half* bHi, const __half* bLo,
    int k0, int tid) {
#pragma unroll
    for (int i = 0; i < 4; i++) {          // A: 2048 chunks
        int idx = tid + i * 512;
        int src = idx >> 10, rem = idx & 1023;
        int row = rem >> 2, c = rem & 3;
        const __half* g = (src ? aLo : aHi) + (size_t)row * D_FF + k0 + c * 8;
        cpasync16(base + src * 20480 + row * 80 + c * 16, g);
    }
#pragma unroll
    for (int i = 0; i < 2; i++) {          // B: 1024 chunks
        int idx = tid + i * 512;
        int src = idx >> 9, rem = idx & 511;
        int row = rem >> 2, c = rem & 3;
        const __half* g = (src ? bLo : bHi) + (size_t)row * D_FF + k0 + c * 8;
        cpasync16(base + 40960 + src * 10240 + row * 80 + c * 16, g);
    }
}

// ---------------- GEMM2: y = h W2^T  (3-term fp16) ----------------
// 512 threads, BM=256, BN=128, warp grid 8M x 2N.
__global__ __launch_bounds__(512, 1) void gemm2_mma() {
    const int e = blockIdx.z;
    const int cnt = g_counts[e];
    const int m0 = blockIdx.x * 256;
    if (m0 >= cnt) return;
    const int n0 = blockIdx.y * 128;
    const int offs = g_offsets[e];
    extern __shared__ char smem[];
    uint32_t sb = s2u(smem);
    const int tid = threadIdx.x, lane = tid & 31, wid = tid >> 5;
    const int wM = wid >> 1, wN = wid & 1;

    const __half* aHi = g_hhi + (size_t)(offs + m0) * D_FF;
    const __half* aLo = g_hlo + (size_t)(offs + m0) * D_FF;
    const size_t wb = (size_t)e * D_MODEL * D_FF + (size_t)n0 * D_FF;
    const __half* bHi = g_w2hi + wb;
    const __half* bLo = g_w2lo + wb;

    g2_load(sb, aHi, aLo, bHi, bLo, 0, tid);   CP_COMMIT();
    g2_load(sb + STAGE2, aHi, aLo, bHi, bLo, 32, tid);  CP_COMMIT();

    float acc[2][8][4] = {};
    const int aRow = lane & 15, aK = (lane >> 4) << 3;
    const int bRow = (lane & 7) | ((lane >> 4) << 3);
    const int bK = ((lane >> 3) & 1) << 3;

    const int NCH = D_FF / 32;  // 128
    for (int j = 0; j < NCH; j++) {
        const int buf = j % 3;
        CP_WAIT1();
        __syncthreads();
        if (j + 2 < NCH)
            g2_load(sb + ((j + 2) % 3) * STAGE2, aHi, aLo, bHi, bLo, (j + 2) * 32, tid);
        CP_COMMIT();
        const uint32_t bA = sb + buf * STAGE2;
#pragma unroll
        for (int kk = 0; kk < 32; kk += 16) {
            uint32_t ah[2][4], al[2][4];
#pragma unroll
            for (int mt = 0; mt < 2; mt++) {
                uint32_t r = wM * 32 + mt * 16 + aRow;
                uint32_t c2 = (kk + aK) * 2;
                ldsm4(ah[mt], bA + r * 80 + c2);
                ldsm4(al[mt], bA + 20480 + r * 80 + c2);
            }
#pragma unroll
            for (int np = 0; np < 4; np++) {
                uint32_t rB = wN * 64 + np * 16 + bRow;
                uint32_t cb2 = (kk + bK) * 2;
                uint32_t bh[4], bl[4];
                ldsm4(bh, bA + 40960 + rB * 80 + cb2);
                ldsm4(bl, bA + 51200 + rB * 80 + cb2);
#pragma unroll
                for (int mt = 0; mt < 2; mt++)
#pragma unroll
                    for (int sub = 0; sub < 2; sub++) {
                        mma16816(acc[mt][np * 2 + sub], ah[mt], bh[sub * 2], bh[sub * 2 + 1]);
                        mma16816(acc[mt][np * 2 + sub], ah[mt], bl[sub * 2], bl[sub * 2 + 1]);
                        mma16816(acc[mt][np * 2 + sub], al[mt], bh[sub * 2], bh[sub * 2 + 1]);
                    }
            }
        }
    }

#pragma unroll
    for (int mt = 0; mt < 2; mt++)
#pragma unroll
        for (int half_ = 0; half_ < 2; half_++) {
            int r = m0 + wM * 32 + mt * 16 + (lane >> 2) + half_ * 8;
            if (r < cnt) {
                size_t rowb = (size_t)(offs + r) * D_MODEL;
#pragma unroll
                for (int nt = 0; nt < 8; nt++) {
                    int col = n0 + wN * 64 + nt * 8 + (lane & 3) * 2;
                    float2 o;
                    o.x = acc[mt][nt][half_ * 2 + 0];
                    o.y = acc[mt][nt][half_ * 2 + 1];
                    *(float2*)(g_y + rowb + col) = o;
                }
            }
        }
}

// ---------------- combine ----------------
__global__ void combine_kernel(const int* kptr, float* __restrict__ out, int T) {
    int tid = blockIdx.x * blockDim.x + threadIdx.x;
    int total = T * (D_MODEL / 4);
    if (tid >= total) return;
    int t = tid / (D_MODEL / 4);
    int c = tid % (D_MODEL / 4);
    int kk = clamp_k(kptr);
    float4 o = make_float4(0.f, 0.f, 0.f, 0.f);
    for (int j = 0; j < kk; j++) {
        int slot = g_tok2slot[t * MAXK + j];
        float w = g_topw[t * MAXK + j];
        float4 yv = *reinterpret_cast<const float4*>(&g_y[(size_t)slot * D_MODEL + c * 4]);
        o.x += w * yv.x; o.y += w * yv.y; o.z += w * yv.z; o.w += w * yv.w;
    }
    *reinterpret_cast<float4*>(&out[(size_t)t * D_MODEL + c * 4]) = o;
}

// ---------------- launch ----------------
extern "C" void kernel_launch(void* const* d_in, const int* in_sizes, int n_in,
                              void* d_out, int out_size) {
    const float* x  = (const float*)d_in[0];
    const float* gW = (const float*)d_in[1];
    const float* gb = (const float*)d_in[2];
    const float* Wg = (const float*)d_in[3];
    const float* W1 = (const float*)d_in[4];
    const float* W2 = (const float*)d_in[5];
    const int* kptr = (n_in > 6) ? (const int*)d_in[6] : nullptr;
    float* out = (float*)d_out;
    const int T = in_sizes[0] / D_MODEL;

    cudaFuncSetAttribute(gemm1_mma, cudaFuncAttributeMaxDynamicSharedMemorySize, 3 * STAGE1);
    cudaFuncSetAttribute(gemm2_mma, cudaFuncAttributeMaxDynamicSharedMemorySize, 3 * STAGE2);

    init_kernel<<<1, 32>>>();
    router_kernel<<<(T + 7) / 8, 256>>>(x, gW, gb, kptr, T);
    offsets_kernel<<<1, 1>>>();
    assign_kernel<<<(T * MAXK + 255) / 256, 256>>>(kptr, T);
    splitx_kernel<<<T * MAXK, 128>>>(x);

    const int n8 = NEXP * D_FF * D_MODEL / 8;
    splitw_kernel<<<4096, 256>>>(Wg, 0, n8);
    splitw_kernel<<<4096, 256>>>(W1, 1, n8);
    splitw_kernel<<<4096, 256>>>(W2, 2, n8);

    gemm1_mma<<<dim3(T / 128, D_FF / 128, NEXP), 512, 3 * STAGE1>>>();
    gemm2_mma<<<dim3(T / 256, D_MODEL / 128, NEXP), 512, 3 * STAGE2>>>();

    combine_kernel<<<(T * (D_MODEL / 4) + 255) / 256, 256>>>(kptr, out, T);
}

// round 9
// speedup vs baseline: 3.9691x; 1.4658x over previous
#include <cuda_runtime.h>
#include <cuda_bf16.h>
#include <cuda_fp16.h>
#include <math.h>
#include <stdint.h>

#define D_MODEL 1024
#define D_FF    4096
#define NEXP    8
#define MAXK    4
#define MAXT    8192
#define MAXSLOTS (MAXT*MAXK)
#define PADS     (MAXSLOTS+256)

typedef unsigned long long ull;

// ---------------- static device scratch ----------------
__device__ int   g_counts[NEXP];
__device__ int   g_cursor[NEXP];
__device__ int   g_offsets[NEXP];
__device__ int   g_slot2tok[MAXSLOTS];
__device__ int   g_tok2slot[MAXSLOTS];
__device__ float g_topw[MAXSLOTS];
__device__ int   g_topidx[MAXSLOTS];

__device__ __align__(256) __half g_wghi[(size_t)NEXP*D_FF*D_MODEL];
__device__ __align__(256) __half g_w1hi[(size_t)NEXP*D_FF*D_MODEL];
__device__ __align__(256) __half g_w2hi[(size_t)NEXP*D_MODEL*D_FF];
__device__ __align__(256) __half g_ahi[(size_t)PADS*D_MODEL];
__device__ __align__(256) __half g_hhi[(size_t)PADS*D_FF];
__device__ __align__(256) __half g_hlo[(size_t)PADS*D_FF];
__device__ __align__(256) float  g_y[(size_t)MAXSLOTS*D_MODEL];

// ---------------- helpers ----------------
__device__ __forceinline__ uint32_t s2u(const void* p) {
    uint32_t a;
    asm("{ .reg .u64 t; cvta.to.shared.u64 t, %1; cvt.u32.u64 %0, t; }"
        : "=r"(a) : "l"(p));
    return a;
}
__device__ __forceinline__ void cpasync16(uint32_t dst, const void* src) {
    asm volatile("cp.async.cg.shared.global [%0], [%1], 16;" :: "r"(dst), "l"(src) : "memory");
}
#define CP_COMMIT() asm volatile("cp.async.commit_group;" ::: "memory")
#define CP_WAIT1()  asm volatile("cp.async.wait_group 1;" ::: "memory")

__device__ __forceinline__ void ldsm4(uint32_t (&r)[4], uint32_t addr) {
    asm volatile("ldmatrix.sync.aligned.m8n8.x4.shared.b16 {%0,%1,%2,%3}, [%4];"
                 : "=r"(r[0]), "=r"(r[1]), "=r"(r[2]), "=r"(r[3]) : "r"(addr));
}
__device__ __forceinline__ void mma16816(float (&c)[4], const uint32_t (&a)[4],
                                         uint32_t b0, uint32_t b1) {
    asm volatile(
        "mma.sync.aligned.m16n8k16.row.col.f32.f16.f16.f32 "
        "{%0,%1,%2,%3}, {%4,%5,%6,%7}, {%8,%9}, {%0,%1,%2,%3};"
        : "+f"(c[0]), "+f"(c[1]), "+f"(c[2]), "+f"(c[3])
        : "r"(a[0]), "r"(a[1]), "r"(a[2]), "r"(a[3]), "r"(b0), "r"(b1));
}

union UH2 { __half2 h; uint32_t u; };
__device__ __forceinline__ uint32_t pack_h2(float a, float b) {
    UH2 v; v.h = __floats2half2_rn(a, b);
    return v.u;
}
__device__ __forceinline__ uint32_t pack_split_h(float a, float b, uint32_t& lo) {
    UH2 h; h.h = __floats2half2_rn(a, b);
    float ra = a - __low2float(h.h);
    float rb = b - __high2float(h.h);
    UH2 l; l.h = __floats2half2_rn(ra, rb);
    lo = l.u;
    return h.u;
}
__device__ __forceinline__ int clamp_k(const int* kptr) {
    int kk = 2;
    if (kptr) { kk = *kptr; kk = kk < 1 ? 1 : (kk > MAXK ? MAXK : kk); }
    return kk;
}

// ---------------- routing kernels ----------------
__global__ void init_kernel() {
    if (threadIdx.x < NEXP) g_counts[threadIdx.x] = 0;
}

__global__ void router_kernel(const float* __restrict__ x,
                              const float* __restrict__ gW,
                              const float* __restrict__ gb,
                              const int* kptr, int T) {
    int gw = (blockIdx.x * blockDim.x + threadIdx.x) >> 5;
    int lane = threadIdx.x & 31;
    if (gw >= T) return;
    const float* xt = x + (size_t)gw * D_MODEL;
    float xr[32];
#pragma unroll
    for (int j = 0; j < 32; j++) xr[j] = xt[lane + j * 32];
    float lg[NEXP];
#pragma unroll
    for (int e = 0; e < NEXP; e++) {
        const float* w = gW + e * D_MODEL;
        float a = 0.f;
#pragma unroll
        for (int j = 0; j < 32; j++) a = fmaf(xr[j], w[lane + j * 32], a);
#pragma unroll
        for (int o = 16; o > 0; o >>= 1) a += __shfl_xor_sync(0xffffffffu, a, o);
        lg[e] = a + gb[e];
    }
    if (lane == 0) {
        int kk = clamp_k(kptr);
        float sc[MAXK]; int sel[MAXK];
        unsigned used = 0;
        for (int j = 0; j < kk; j++) {
            float bv = -3.0e38f; int bi = 0;
            for (int e = 0; e < NEXP; e++)
                if (!((used >> e) & 1u) && lg[e] > bv) { bv = lg[e]; bi = e; }
            used |= 1u << bi; sel[j] = bi; sc[j] = bv;
        }
        float m = sc[0], s = 0.f, p[MAXK];
        for (int j = 0; j < kk; j++) { p[j] = __expf(sc[j] - m); s += p[j]; }
        float inv = 1.f / s;
        for (int j = 0; j < kk; j++) {
            g_topidx[gw * MAXK + j] = sel[j];
            g_topw[gw * MAXK + j] = p[j] * inv;
            atomicAdd(&g_counts[sel[j]], 1);
        }
    }
}

__global__ void offsets_kernel() {
    if (threadIdx.x == 0 && blockIdx.x == 0) {
        int off = 0;
        for (int e = 0; e < NEXP; e++) { g_offsets[e] = off; off += g_counts[e]; g_cursor[e] = 0; }
    }
}

__global__ void assign_kernel(const int* kptr, int T) {
    int tid = blockIdx.x * blockDim.x + threadIdx.x;
    if (tid >= T * MAXK) return;
    int t = tid / MAXK, j = tid % MAXK;
    int kk = clamp_k(kptr);
    if (j >= kk) return;
    int e = g_topidx[t * MAXK + j];
    int r = atomicAdd(&g_cursor[e], 1);
    int slot = g_offsets[e] + r;
    g_slot2tok[slot] = t;
    g_tok2slot[t * MAXK + j] = slot;
}

// ---------------- conversion kernels (fp32 -> fp16 hi) ----------------
__global__ void convw_kernel(const float* __restrict__ src, int which, int n8) {
    __half* hi = which == 0 ? g_wghi : which == 1 ? g_w1hi : g_w2hi;
    for (int i = blockIdx.x * blockDim.x + threadIdx.x; i < n8; i += gridDim.x * blockDim.x) {
        const float4* s = (const float4*)src + (size_t)i * 2;
        float4 a = s[0], b = s[1];
        ((uint4*)hi)[i] = make_uint4(pack_h2(a.x, a.y), pack_h2(a.z, a.w),
                                     pack_h2(b.x, b.y), pack_h2(b.z, b.w));
    }
}

__global__ void convx_kernel(const float* __restrict__ x) {
    int slot = blockIdx.x;
    int total = g_offsets[NEXP - 1] + g_counts[NEXP - 1];
    if (slot >= total) return;
    int tok = g_slot2tok[slot];
    int t = threadIdx.x;   // 128 threads x 8 floats
    const float4* s = (const float4*)(x + (size_t)tok * D_MODEL) + t * 2;
    float4 a = s[0], b = s[1];
    ((uint4*)(g_ahi + (size_t)slot * D_MODEL))[t] =
        make_uint4(pack_h2(a.x, a.y), pack_h2(a.z, a.w),
                   pack_h2(b.x, b.y), pack_h2(b.z, b.w));
}

// ---------------- GEMM tiling ----------------
// smem row pitch = 80 bytes (32 fp16 + 8 pad), ldmatrix conflict-free (proven R6/R7)
#define STAGE1 30720
#define STAGE2 51200

// GEMM1 stage: A[128x32]@0, Bg[128x32]@10240, Bv[128x32]@20480
__device__ __forceinline__ void g1_load(
    uint32_t base, const __half* aHi, const __half* bg, const __half* bv,
    int k0, int tid) {
#pragma unroll
    for (int i = 0; i < 3; i++) {          // 1536 chunks of 16B
        int idx = tid + i * 512;
        int mat = idx >> 9, rem = idx & 511;
        int row = rem >> 2, c = rem & 3;
        const __half* g = (mat == 0 ? aHi : mat == 1 ? bg : bv)
                          + (size_t)row * D_MODEL + k0 + c * 8;
        cpasync16(base + mat * 10240 + row * 80 + c * 16, g);
    }
}

// ---------------- GEMM1: G = X Wg^T, V = X W1^T, h = silu(G)*V ----------------
// 1-term fp16. 512 threads, warp grid 4M x 4N, tile 128x128.
__global__ __launch_bounds__(512, 1) void gemm1_mma() {
    const int e = blockIdx.z;
    const int cnt = g_counts[e];
    const int m0 = blockIdx.x * 128;
    if (m0 >= cnt) return;
    const int n0 = blockIdx.y * 128;
    const int offs = g_offsets[e];
    extern __shared__ char smem[];
    uint32_t sb = s2u(smem);
    const int tid = threadIdx.x, lane = tid & 31, wid = tid >> 5;
    const int wM = wid >> 2, wN = wid & 3;

    const __half* aHi = g_ahi + (size_t)(offs + m0) * D_MODEL;
    const size_t wb = (size_t)e * D_FF * D_MODEL + (size_t)n0 * D_MODEL;
    const __half* bg = g_wghi + wb;
    const __half* bv = g_w1hi + wb;

    g1_load(sb, aHi, bg, bv, 0, tid);   CP_COMMIT();
    g1_load(sb + STAGE1, aHi, bg, bv, 32, tid);  CP_COMMIT();

    float accG[2][4][4] = {}, accV[2][4][4] = {};
    const int aRow = lane & 15, aK = (lane >> 4) << 3;
    const int bRow = (lane & 7) | ((lane >> 4) << 3);
    const int bK = ((lane >> 3) & 1) << 3;

    const int NCH = D_MODEL / 32;  // 32
    for (int j = 0; j < NCH; j++) {
        const int buf = j % 3;
        CP_WAIT1();
        __syncthreads();
        if (j + 2 < NCH)
            g1_load(sb + ((j + 2) % 3) * STAGE1, aHi, bg, bv, (j + 2) * 32, tid);
        CP_COMMIT();
        const uint32_t bA = sb + buf * STAGE1;
#pragma unroll
        for (int kk = 0; kk < 32; kk += 16) {
            uint32_t ah[2][4];
#pragma unroll
            for (int mt = 0; mt < 2; mt++) {
                uint32_t r = wM * 32 + mt * 16 + aRow;
                ldsm4(ah[mt], bA + r * 80 + (kk + aK) * 2);
            }
#pragma unroll
            for (int np = 0; np < 2; np++) {
                uint32_t rN = wN * 32 + np * 16 + bRow;
                uint32_t cb2 = (kk + bK) * 2;
                uint32_t bgf[4], bvf[4];
                ldsm4(bgf, bA + 10240 + rN * 80 + cb2);
                ldsm4(bvf, bA + 20480 + rN * 80 + cb2);
#pragma unroll
                for (int mt = 0; mt < 2; mt++)
#pragma unroll
                    for (int sub = 0; sub < 2; sub++) {
                        mma16816(accG[mt][np * 2 + sub], ah[mt], bgf[sub * 2], bgf[sub * 2 + 1]);
                        mma16816(accV[mt][np * 2 + sub], ah[mt], bvf[sub * 2], bvf[sub * 2 + 1]);
                    }
            }
        }
    }

#pragma unroll
    for (int mt = 0; mt < 2; mt++)
#pragma unroll
        for (int half_ = 0; half_ < 2; half_++) {
            int r = m0 + wM * 32 + mt * 16 + (lane >> 2) + half_ * 8;
            if (r < cnt) {
                size_t rowb = (size_t)(offs + r) * D_FF;
#pragma unroll
                for (int nt = 0; nt < 4; nt++) {
                    float gg0 = accG[mt][nt][half_ * 2 + 0];
                    float gg1 = accG[mt][nt][half_ * 2 + 1];
                    float vv0 = accV[mt][nt][half_ * 2 + 0];
                    float vv1 = accV[mt][nt][half_ * 2 + 1];
                    float h0 = gg0 / (1.f + __expf(-gg0)) * vv0;
                    float h1 = gg1 / (1.f + __expf(-gg1)) * vv1;
                    uint32_t lo, hi = pack_split_h(h0, h1, lo);
                    int col = n0 + wN * 32 + nt * 8 + (lane & 3) * 2;
                    *(uint32_t*)(g_hhi + rowb + col) = hi;
                    *(uint32_t*)(g_hlo + rowb + col) = lo;
                }
            }
        }
}

// GEMM2 stage: A_hi[256x32]@0, A_lo@20480, B_hi[128x32]@40960
__device__ __forceinline__ void g2_load(
    uint32_t base, const __half* aHi, const __half* aLo, const __half* bHi,
    int k0, int tid) {
#pragma unroll
    for (int i = 0; i < 5; i++) {          // 2560 chunks
        int idx = tid + i * 512;
        if (idx < 2048) {                  // A hi/lo
            int src = idx >> 10, rem = idx & 1023;
            int row = rem >> 2, c = rem & 3;
            const __half* g = (src ? aLo : aHi) + (size_t)row * D_FF + k0 + c * 8;
            cpasync16(base + src * 20480 + row * 80 + c * 16, g);
        } else {                           // B hi
            int rem = idx - 2048;
            int row = rem >> 2, c = rem & 3;
            cpasync16(base + 40960 + row * 80 + c * 16,
                      bHi + (size_t)row * D_FF + k0 + c * 8);
        }
    }
}

// ---------------- GEMM2: y = h W2^T  (2-term: (h_hi + h_lo) * W2_hi) ----------------
// 512 threads, BM=256, BN=128, warp grid 8M x 2N.
__global__ __launch_bounds__(512, 1) void gemm2_mma() {
    const int e = blockIdx.z;
    const int cnt = g_counts[e];
    const int m0 = blockIdx.x * 256;
    if (m0 >= cnt) return;
    const int n0 = blockIdx.y * 128;
    const int offs = g_offsets[e];
    extern __shared__ char smem[];
    uint32_t sb = s2u(smem);
    const int tid = threadIdx.x, lane = tid & 31, wid = tid >> 5;
    const int wM = wid >> 1, wN = wid & 1;

    const __half* aHi = g_hhi + (size_t)(offs + m0) * D_FF;
    const __half* aLo = g_hlo + (size_t)(offs + m0) * D_FF;
    const __half* bHi = g_w2hi + (size_t)e * D_MODEL * D_FF + (size_t)n0 * D_FF;

    g2_load(sb, aHi, aLo, bHi, 0, tid);   CP_COMMIT();
    g2_load(sb + STAGE2, aHi, aLo, bHi, 32, tid);  CP_COMMIT();

    float acc[2][8][4] = {};
    const int aRow = lane & 15, aK = (lane >> 4) << 3;
    const int bRow = (lane & 7) | ((lane >> 4) << 3);
    const int bK = ((lane >> 3) & 1) << 3;

    const int NCH = D_FF / 32;  // 128
    for (int j = 0; j < NCH; j++) {
        const int buf = j % 3;
        CP_WAIT1();
        __syncthreads();
        if (j + 2 < NCH)
            g2_load(sb + ((j + 2) % 3) * STAGE2, aHi, aLo, bHi, (j + 2) * 32, tid);
        CP_COMMIT();
        const uint32_t bA = sb + buf * STAGE2;
#pragma unroll
        for (int kk = 0; kk < 32; kk += 16) {
            uint32_t ah[2][4], al[2][4];
#pragma unroll
            for (int mt = 0; mt < 2; mt++) {
                uint32_t r = wM * 32 + mt * 16 + aRow;
                uint32_t c2 = (kk + aK) * 2;
                ldsm4(ah[mt], bA + r * 80 + c2);
                ldsm4(al[mt], bA + 20480 + r * 80 + c2);
            }
#pragma unroll
            for (int np = 0; np < 4; np++) {
                uint32_t rB = wN * 64 + np * 16 + bRow;
                uint32_t cb2 = (kk + bK) * 2;
                uint32_t bh[4];
                ldsm4(bh, bA + 40960 + rB * 80 + cb2);
#pragma unroll
                for (int mt = 0; mt < 2; mt++)
#pragma unroll
                    for (int sub = 0; sub < 2; sub++) {
                        mma16816(acc[mt][np * 2 + sub], ah[mt], bh[sub * 2], bh[sub * 2 + 1]);
                        mma16816(acc[mt][np * 2 + sub], al[mt], bh[sub * 2], bh[sub * 2 + 1]);
                    }
            }
        }
    }

#pragma unroll
    for (int mt = 0; mt < 2; mt++)
#pragma unroll
        for (int half_ = 0; half_ < 2; half_++) {
            int r = m0 + wM * 32 + mt * 16 + (lane >> 2) + half_ * 8;
            if (r < cnt) {
                size_t rowb = (size_t)(offs + r) * D_MODEL;
#pragma unroll
                for (int nt = 0; nt < 8; nt++) {
                    int col = n0 + wN * 64 + nt * 8 + (lane & 3) * 2;
                    float2 o;
                    o.x = acc[mt][nt][half_ * 2 + 0];
                    o.y = acc[mt][nt][half_ * 2 + 1];
                    *(float2*)(g_y + rowb + col) = o;
                }
            }
        }
}

// ---------------- combine ----------------
__global__ void combine_kernel(const int* kptr, float* __restrict__ out, int T) {
    int tid = blockIdx.x * blockDim.x + threadIdx.x;
    int total = T * (D_MODEL / 4);
    if (tid >= total) return;
    int t = tid / (D_MODEL / 4);
    int c = tid % (D_MODEL / 4);
    int kk = clamp_k(kptr);
    float4 o = make_float4(0.f, 0.f, 0.f, 0.f);
    for (int j = 0; j < kk; j++) {
        int slot = g_tok2slot[t * MAXK + j];
        float w = g_topw[t * MAXK + j];
        float4 yv = *reinterpret_cast<const float4*>(&g_y[(size_t)slot * D_MODEL + c * 4]);
        o.x += w * yv.x; o.y += w * yv.y; o.z += w * yv.z; o.w += w * yv.w;
    }
    *reinterpret_cast<float4*>(&out[(size_t)t * D_MODEL + c * 4]) = o;
}

// ---------------- launch ----------------
extern "C" void kernel_launch(void* const* d_in, const int* in_sizes, int n_in,
                              void* d_out, int out_size) {
    const float* x  = (const float*)d_in[0];
    const float* gW = (const float*)d_in[1];
    const float* gb = (const float*)d_in[2];
    const float* Wg = (const float*)d_in[3];
    const float* W1 = (const float*)d_in[4];
    const float* W2 = (const float*)d_in[5];
    const int* kptr = (n_in > 6) ? (const int*)d_in[6] : nullptr;
    float* out = (float*)d_out;
    const int T = in_sizes[0] / D_MODEL;

    cudaFuncSetAttribute(gemm1_mma, cudaFuncAttributeMaxDynamicSharedMemorySize, 3 * STAGE1);
    cudaFuncSetAttribute(gemm2_mma, cudaFuncAttributeMaxDynamicSharedMemorySize, 3 * STAGE2);

    init_kernel<<<1, 32>>>();
    router_kernel<<<(T + 7) / 8, 256>>>(x, gW, gb, kptr, T);
    offsets_kernel<<<1, 1>>>();
    assign_kernel<<<(T * MAXK + 255) / 256, 256>>>(kptr, T);
    convx_kernel<<<T * MAXK, 128>>>(x);

    const int n8 = NEXP * D_FF * D_MODEL / 8;
    convw_kernel<<<4096, 256>>>(Wg, 0, n8);
    convw_kernel<<<4096, 256>>>(W1, 1, n8);
    convw_kernel<<<4096, 256>>>(W2, 2, n8);

    gemm1_mma<<<dim3(T / 128, D_FF / 128, NEXP), 512, 3 * STAGE1>>>();
    gemm2_mma<<<dim3(T / 256, D_MODEL / 128, NEXP), 512, 3 * STAGE2>>>();

    combine_kernel<<<(T * (D_MODEL / 4) + 255) / 256, 256>>>(kptr, out, T);
}

// round 10
// speedup vs baseline: 4.8528x; 1.2226x over previous
#include <cuda_runtime.h>
#include <cuda_bf16.h>
#include <cuda_fp16.h>
#include <math.h>
#include <stdint.h>

#define D_MODEL 1024
#define D_FF    4096
#define NEXP    8
#define MAXK    4
#define MAXT    8192
#define MAXSLOTS (MAXT*MAXK)
#define PADS     (MAXSLOTS+256)

typedef unsigned long long ull;

// ---------------- static device scratch ----------------
__device__ int   g_counts[NEXP];
__device__ int   g_cursor[NEXP];
__device__ int   g_offsets[NEXP];
__device__ int   g_slot2tok[MAXSLOTS];
__device__ float g_slotw[MAXSLOTS];
__device__ float g_topw[MAXSLOTS];
__device__ int   g_topidx[MAXSLOTS];

__device__ __align__(256) __half g_wghi[(size_t)NEXP*D_FF*D_MODEL];
__device__ __align__(256) __half g_w1hi[(size_t)NEXP*D_FF*D_MODEL];
__device__ __align__(256) __half g_w2hi[(size_t)NEXP*D_MODEL*D_FF];
__device__ __align__(256) __half g_ahi[(size_t)PADS*D_MODEL];
__device__ __align__(256) __half g_hhi[(size_t)PADS*D_FF];

// ---------------- helpers ----------------
__device__ __forceinline__ uint32_t s2u(const void* p) {
    uint32_t a;
    asm("{ .reg .u64 t; cvta.to.shared.u64 t, %1; cvt.u32.u64 %0, t; }"
        : "=r"(a) : "l"(p));
    return a;
}
__device__ __forceinline__ void cpasync16(uint32_t dst, const void* src) {
    asm volatile("cp.async.cg.shared.global [%0], [%1], 16;" :: "r"(dst), "l"(src) : "memory");
}
#define CP_COMMIT() asm volatile("cp.async.commit_group;" ::: "memory")
#define CP_WAIT1()  asm volatile("cp.async.wait_group 1;" ::: "memory")

__device__ __forceinline__ void ldsm4(uint32_t (&r)[4], uint32_t addr) {
    asm volatile("ldmatrix.sync.aligned.m8n8.x4.shared.b16 {%0,%1,%2,%3}, [%4];"
                 : "=r"(r[0]), "=r"(r[1]), "=r"(r[2]), "=r"(r[3]) : "r"(addr));
}
__device__ __forceinline__ void mma16816(float (&c)[4], const uint32_t (&a)[4],
                                         uint32_t b0, uint32_t b1) {
    asm volatile(
        "mma.sync.aligned.m16n8k16.row.col.f32.f16.f16.f32 "
        "{%0,%1,%2,%3}, {%4,%5,%6,%7}, {%8,%9}, {%0,%1,%2,%3};"
        : "+f"(c[0]), "+f"(c[1]), "+f"(c[2]), "+f"(c[3])
        : "r"(a[0]), "r"(a[1]), "r"(a[2]), "r"(a[3]), "r"(b0), "r"(b1));
}

union UH2 { __half2 h; uint32_t u; };
__device__ __forceinline__ uint32_t pack_h2(float a, float b) {
    UH2 v; v.h = __floats2half2_rn(a, b);
    return v.u;
}
__device__ __forceinline__ int clamp_k(const int* kptr) {
    int kk = 2;
    if (kptr) { kk = *kptr; kk = kk < 1 ? 1 : (kk > MAXK ? MAXK : kk); }
    return kk;
}

// ---------------- routing kernels ----------------
__global__ void init_kernel() {
    if (threadIdx.x < NEXP) g_counts[threadIdx.x] = 0;
}

__global__ void zero_out_kernel(float* __restrict__ out, int n4) {
    int i = blockIdx.x * blockDim.x + threadIdx.x;
    if (i < n4) ((float4*)out)[i] = make_float4(0.f, 0.f, 0.f, 0.f);
}

__global__ void router_kernel(const float* __restrict__ x,
                              const float* __restrict__ gW,
                              const float* __restrict__ gb,
                              const int* kptr, int T) {
    int gw = (blockIdx.x * blockDim.x + threadIdx.x) >> 5;
    int lane = threadIdx.x & 31;
    if (gw >= T) return;
    const float* xt = x + (size_t)gw * D_MODEL;
    float xr[32];
#pragma unroll
    for (int j = 0; j < 32; j++) xr[j] = xt[lane + j * 32];
    float lg[NEXP];
#pragma unroll
    for (int e = 0; e < NEXP; e++) {
        const float* w = gW + e * D_MODEL;
        float a = 0.f;
#pragma unroll
        for (int j = 0; j < 32; j++) a = fmaf(xr[j], w[lane + j * 32], a);
#pragma unroll
        for (int o = 16; o > 0; o >>= 1) a += __shfl_xor_sync(0xffffffffu, a, o);
        lg[e] = a + gb[e];
    }
    if (lane == 0) {
        int kk = clamp_k(kptr);
        float sc[MAXK]; int sel[MAXK];
        unsigned used = 0;
        for (int j = 0; j < kk; j++) {
            float bv = -3.0e38f; int bi = 0;
            for (int e = 0; e < NEXP; e++)
                if (!((used >> e) & 1u) && lg[e] > bv) { bv = lg[e]; bi = e; }
            used |= 1u << bi; sel[j] = bi; sc[j] = bv;
        }
        float m = sc[0], s = 0.f, p[MAXK];
        for (int j = 0; j < kk; j++) { p[j] = __expf(sc[j] - m); s += p[j]; }
        float inv = 1.f / s;
        for (int j = 0; j < kk; j++) {
            g_topidx[gw * MAXK + j] = sel[j];
            g_topw[gw * MAXK + j] = p[j] * inv;
            atomicAdd(&g_counts[sel[j]], 1);
        }
    }
}

__global__ void offsets_kernel() {
    if (threadIdx.x == 0 && blockIdx.x == 0) {
        int off = 0;
        for (int e = 0; e < NEXP; e++) { g_offsets[e] = off; off += g_counts[e]; g_cursor[e] = 0; }
    }
}

__global__ void assign_kernel(const int* kptr, int T) {
    int tid = blockIdx.x * blockDim.x + threadIdx.x;
    if (tid >= T * MAXK) return;
    int t = tid / MAXK, j = tid % MAXK;
    int kk = clamp_k(kptr);
    if (j >= kk) return;
    int e = g_topidx[t * MAXK + j];
    int r = atomicAdd(&g_cursor[e], 1);
    int slot = g_offsets[e] + r;
    g_slot2tok[slot] = t;
    g_slotw[slot] = g_topw[t * MAXK + j];
}

// ---------------- conversion kernels (fp32 -> fp16) ----------------
__global__ void convw_kernel(const float* __restrict__ src, int which, int n8) {
    __half* hi = which == 0 ? g_wghi : which == 1 ? g_w1hi : g_w2hi;
    for (int i = blockIdx.x * blockDim.x + threadIdx.x; i < n8; i += gridDim.x * blockDim.x) {
        const float4* s = (const float4*)src + (size_t)i * 2;
        float4 a = s[0], b = s[1];
        ((uint4*)hi)[i] = make_uint4(pack_h2(a.x, a.y), pack_h2(a.z, a.w),
                                     pack_h2(b.x, b.y), pack_h2(b.z, b.w));
    }
}

__global__ void convx_kernel(const float* __restrict__ x) {
    int slot = blockIdx.x;
    int total = g_offsets[NEXP - 1] + g_counts[NEXP - 1];
    if (slot >= total) return;
    int tok = g_slot2tok[slot];
    int t = threadIdx.x;   // 128 threads x 8 floats
    const float4* s = (const float4*)(x + (size_t)tok * D_MODEL) + t * 2;
    float4 a = s[0], b = s[1];
    ((uint4*)(g_ahi + (size_t)slot * D_MODEL))[t] =
        make_uint4(pack_h2(a.x, a.y), pack_h2(a.z, a.w),
                   pack_h2(b.x, b.y), pack_h2(b.z, b.w));
}

// ---------------- GEMM tiling ----------------
// smem row pitch = 80 bytes (32 fp16 + 8 pad), ldmatrix conflict-free (proven R6-R9)
#define STAGE1 30720
#define STAGE2 30720

// GEMM1 stage: A[128x32]@0, Bg[128x32]@10240, Bv[128x32]@20480
__device__ __forceinline__ void g1_load(
    uint32_t base, const __half* aHi, const __half* bg, const __half* bv,
    int k0, int tid) {
#pragma unroll
    for (int i = 0; i < 3; i++) {          // 1536 chunks of 16B
        int idx = tid + i * 512;
        int mat = idx >> 9, rem = idx & 511;
        int row = rem >> 2, c = rem & 3;
        const __half* g = (mat == 0 ? aHi : mat == 1 ? bg : bv)
                          + (size_t)row * D_MODEL + k0 + c * 8;
        cpasync16(base + mat * 10240 + row * 80 + c * 16, g);
    }
}

// ---------------- GEMM1: G = X Wg^T, V = X W1^T, h = silu(G)*V ----------------
// 1-term fp16. 512 threads, warp grid 4M x 4N, tile 128x128.
__global__ __launch_bounds__(512, 1) void gemm1_mma() {
    const int e = blockIdx.z;
    const int cnt = g_counts[e];
    const int m0 = blockIdx.x * 128;
    if (m0 >= cnt) return;
    const int n0 = blockIdx.y * 128;
    const int offs = g_offsets[e];
    extern __shared__ char smem[];
    uint32_t sb = s2u(smem);
    const int tid = threadIdx.x, lane = tid & 31, wid = tid >> 5;
    const int wM = wid >> 2, wN = wid & 3;

    const __half* aHi = g_ahi + (size_t)(offs + m0) * D_MODEL;
    const size_t wb = (size_t)e * D_FF * D_MODEL + (size_t)n0 * D_MODEL;
    const __half* bg = g_wghi + wb;
    const __half* bv = g_w1hi + wb;

    g1_load(sb, aHi, bg, bv, 0, tid);   CP_COMMIT();
    g1_load(sb + STAGE1, aHi, bg, bv, 32, tid);  CP_COMMIT();

    float accG[2][4][4] = {}, accV[2][4][4] = {};
    const int aRow = lane & 15, aK = (lane >> 4) << 3;
    const int bRow = (lane & 7) | ((lane >> 4) << 3);
    const int bK = ((lane >> 3) & 1) << 3;

    const int NCH = D_MODEL / 32;  // 32
    for (int j = 0; j < NCH; j++) {
        const int buf = j % 3;
        CP_WAIT1();
        __syncthreads();
        if (j + 2 < NCH)
            g1_load(sb + ((j + 2) % 3) * STAGE1, aHi, bg, bv, (j + 2) * 32, tid);
        CP_COMMIT();
        const uint32_t bA = sb + buf * STAGE1;
#pragma unroll
        for (int kk = 0; kk < 32; kk += 16) {
            uint32_t ah[2][4];
#pragma unroll
            for (int mt = 0; mt < 2; mt++) {
                uint32_t r = wM * 32 + mt * 16 + aRow;
                ldsm4(ah[mt], bA + r * 80 + (kk + aK) * 2);
            }
#pragma unroll
            for (int np = 0; np < 2; np++) {
                uint32_t rN = wN * 32 + np * 16 + bRow;
                uint32_t cb2 = (kk + bK) * 2;
                uint32_t bgf[4], bvf[4];
                ldsm4(bgf, bA + 10240 + rN * 80 + cb2);
                ldsm4(bvf, bA + 20480 + rN * 80 + cb2);
#pragma unroll
                for (int mt = 0; mt < 2; mt++)
#pragma unroll
                    for (int sub = 0; sub < 2; sub++) {
                        mma16816(accG[mt][np * 2 + sub], ah[mt], bgf[sub * 2], bgf[sub * 2 + 1]);
                        mma16816(accV[mt][np * 2 + sub], ah[mt], bvf[sub * 2], bvf[sub * 2 + 1]);
                    }
            }
        }
    }

#pragma unroll
    for (int mt = 0; mt < 2; mt++)
#pragma unroll
        for (int half_ = 0; half_ < 2; half_++) {
            int r = m0 + wM * 32 + mt * 16 + (lane >> 2) + half_ * 8;
            if (r < cnt) {
                size_t rowb = (size_t)(offs + r) * D_FF;
#pragma unroll
                for (int nt = 0; nt < 4; nt++) {
                    float gg0 = accG[mt][nt][half_ * 2 + 0];
                    float gg1 = accG[mt][nt][half_ * 2 + 1];
                    float vv0 = accV[mt][nt][half_ * 2 + 0];
                    float vv1 = accV[mt][nt][half_ * 2 + 1];
                    float h0 = gg0 / (1.f + __expf(-gg0)) * vv0;
                    float h1 = gg1 / (1.f + __expf(-gg1)) * vv1;
                    int col = n0 + wN * 32 + nt * 8 + (lane & 3) * 2;
                    *(uint32_t*)(g_hhi + rowb + col) = pack_h2(h0, h1);
                }
            }
        }
}

// GEMM2 stage: A[256x32]@0 (20480 B), B[128x32]@20480 (10240 B)
__device__ __forceinline__ void g2_load(
    uint32_t base, const __half* aHi, const __half* bHi, int k0, int tid) {
#pragma unroll
    for (int i = 0; i < 3; i++) {          // 1536 chunks
        int idx = tid + i * 512;
        if (idx < 1024) {                  // A: 256 rows x 4 chunks
            int row = idx >> 2, c = idx & 3;
            cpasync16(base + row * 80 + c * 16,
                      aHi + (size_t)row * D_FF + k0 + c * 8);
        } else {                           // B: 128 rows x 4 chunks
            int rem = idx - 1024;
            int row = rem >> 2, c = rem & 3;
            cpasync16(base + 20480 + row * 80 + c * 16,
                      bHi + (size_t)row * D_FF + k0 + c * 8);
        }
    }
}

// ---------------- GEMM2: y = h W2^T, fused weighted scatter into out ----------------
// 1-term fp16. 512 threads, BM=256, BN=128, warp grid 8M x 2N.
__global__ __launch_bounds__(512, 1) void gemm2_mma(float* __restrict__ out) {
    const int e = blockIdx.z;
    const int cnt = g_counts[e];
    const int m0 = blockIdx.x * 256;
    if (m0 >= cnt) return;
    const int n0 = blockIdx.y * 128;
    const int offs = g_offsets[e];
    extern __shared__ char smem[];
    uint32_t sb = s2u(smem);
    const int tid = threadIdx.x, lane = tid & 31, wid = tid >> 5;
    const int wM = wid >> 1, wN = wid & 1;

    const __half* aHi = g_hhi + (size_t)(offs + m0) * D_FF;
    const __half* bHi = g_w2hi + (size_t)e * D_MODEL * D_FF + (size_t)n0 * D_FF;

    g2_load(sb, aHi, bHi, 0, tid);   CP_COMMIT();
    g2_load(sb + STAGE2, aHi, bHi, 32, tid);  CP_COMMIT();

    float acc[2][8][4] = {};
    const int aRow = lane & 15, aK = (lane >> 4) << 3;
    const int bRow = (lane & 7) | ((lane >> 4) << 3);
    const int bK = ((lane >> 3) & 1) << 3;

    const int NCH = D_FF / 32;  // 128
    for (int j = 0; j < NCH; j++) {
        const int buf = j % 3;
        CP_WAIT1();
        __syncthreads();
        if (j + 2 < NCH)
            g2_load(sb + ((j + 2) % 3) * STAGE2, aHi, bHi, (j + 2) * 32, tid);
        CP_COMMIT();
        const uint32_t bA = sb + buf * STAGE2;
#pragma unroll
        for (int kk = 0; kk < 32; kk += 16) {
            uint32_t ah[2][4];
#pragma unroll
            for (int mt = 0; mt < 2; mt++) {
                uint32_t r = wM * 32 + mt * 16 + aRow;
                ldsm4(ah[mt], bA + r * 80 + (kk + aK) * 2);
            }
#pragma unroll
            for (int np = 0; np < 4; np++) {
                uint32_t rB = wN * 64 + np * 16 + bRow;
                uint32_t bh[4];
                ldsm4(bh, bA + 20480 + rB * 80 + (kk + bK) * 2);
#pragma unroll
                for (int mt = 0; mt < 2; mt++)
#pragma unroll
                    for (int sub = 0; sub < 2; sub++)
                        mma16816(acc[mt][np * 2 + sub], ah[mt], bh[sub * 2], bh[sub * 2 + 1]);
            }
        }
    }

    // epilogue: out[tok] += w_slot * y_row  (k=2 contributions per token: bit-deterministic)
#pragma unroll
    for (int mt = 0; mt < 2; mt++)
#pragma unroll
        for (int half_ = 0; half_ < 2; half_++) {
            int r = m0 + wM * 32 + mt * 16 + (lane >> 2) + half_ * 8;
            if (r < cnt) {
                int tok = g_slot2tok[offs + r];
                float w = g_slotw[offs + r];
                float* orow = out + (size_t)tok * D_MODEL;
#pragma unroll
                for (int nt = 0; nt < 8; nt++) {
                    int col = n0 + wN * 64 + nt * 8 + (lane & 3) * 2;
                    atomicAdd(&orow[col],     w * acc[mt][nt][half_ * 2 + 0]);
                    atomicAdd(&orow[col + 1], w * acc[mt][nt][half_ * 2 + 1]);
                }
            }
        }
}

// ---------------- launch ----------------
extern "C" void kernel_launch(void* const* d_in, const int* in_sizes, int n_in,
                              void* d_out, int out_size) {
    const float* x  = (const float*)d_in[0];
    const float* gW = (const float*)d_in[1];
    const float* gb = (const float*)d_in[2];
    const float* Wg = (const float*)d_in[3];
    const float* W1 = (const float*)d_in[4];
    const float* W2 = (const float*)d_in[5];
    const int* kptr = (n_in > 6) ? (const int*)d_in[6] : nullptr;
    float* out = (float*)d_out;
    const int T = in_sizes[0] / D_MODEL;

    cudaFuncSetAttribute(gemm1_mma, cudaFuncAttributeMaxDynamicSharedMemorySize, 3 * STAGE1);
    cudaFuncSetAttribute(gemm2_mma, cudaFuncAttributeMaxDynamicSharedMemorySize, 3 * STAGE2);

    init_kernel<<<1, 32>>>();
    zero_out_kernel<<<(out_size / 4 + 255) / 256, 256>>>(out, out_size / 4);
    router_kernel<<<(T + 7) / 8, 256>>>(x, gW, gb, kptr, T);
    offsets_kernel<<<1, 1>>>();
    assign_kernel<<<(T * MAXK + 255) / 256, 256>>>(kptr, T);
    convx_kernel<<<T * MAXK, 128>>>(x);

    const int n8 = NEXP * D_FF * D_MODEL / 8;
    convw_kernel<<<4096, 256>>>(Wg, 0, n8);
    convw_kernel<<<4096, 256>>>(W1, 1, n8);
    convw_kernel<<<4096, 256>>>(W2, 2, n8);

    gemm1_mma<<<dim3(T / 128, D_FF / 128, NEXP), 512, 3 * STAGE1>>>();
    gemm2_mma<<<dim3(T / 256, D_MODEL / 128, NEXP), 512, 3 * STAGE2>>>(out);
}

// round 11
// speedup vs baseline: 5.8193x; 1.1991x over previous
#include <cuda_runtime.h>
#include <cuda_bf16.h>
#include <cuda_fp16.h>
#include <math.h>
#include <stdint.h>

#define D_MODEL 1024
#define D_FF    4096
#define NEXP    8
#define MAXK    4
#define MAXT    8192
#define MAXSLOTS (MAXT*MAXK)
#define PADS     (MAXSLOTS+256)

typedef unsigned long long ull;

// ---------------- static device scratch ----------------
__device__ int   g_counts[NEXP];
__device__ int   g_cursor[NEXP];
__device__ int   g_offsets[NEXP];
__device__ int   g_slot2tok[MAXSLOTS];
__device__ float g_slotw[MAXSLOTS];
__device__ float g_topw[MAXSLOTS];
__device__ int   g_topidx[MAXSLOTS];

__device__ __align__(256) __half g_wghi[(size_t)NEXP*D_FF*D_MODEL];
__device__ __align__(256) __half g_w1hi[(size_t)NEXP*D_FF*D_MODEL];
__device__ __align__(256) __half g_w2hi[(size_t)NEXP*D_MODEL*D_FF];
__device__ __align__(256) __half g_ahi[(size_t)PADS*D_MODEL];
__device__ __align__(256) __half g_hhi[(size_t)PADS*D_FF];

// ---------------- helpers ----------------
__device__ __forceinline__ uint32_t s2u(const void* p) {
    uint32_t a;
    asm("{ .reg .u64 t; cvta.to.shared.u64 t, %1; cvt.u32.u64 %0, t; }"
        : "=r"(a) : "l"(p));
    return a;
}
__device__ __forceinline__ void cpasync16(uint32_t dst, const void* src) {
    asm volatile("cp.async.cg.shared.global [%0], [%1], 16;" :: "r"(dst), "l"(src) : "memory");
}
#define CP_COMMIT() asm volatile("cp.async.commit_group;" ::: "memory")
#define CP_WAIT2()  asm volatile("cp.async.wait_group 2;" ::: "memory")

__device__ __forceinline__ void ldsm4(uint32_t (&r)[4], uint32_t addr) {
    asm volatile("ldmatrix.sync.aligned.m8n8.x4.shared.b16 {%0,%1,%2,%3}, [%4];"
                 : "=r"(r[0]), "=r"(r[1]), "=r"(r[2]), "=r"(r[3]) : "r"(addr));
}
__device__ __forceinline__ void mma16816(float (&c)[4], const uint32_t (&a)[4],
                                         uint32_t b0, uint32_t b1) {
    asm volatile(
        "mma.sync.aligned.m16n8k16.row.col.f32.f16.f16.f32 "
        "{%0,%1,%2,%3}, {%4,%5,%6,%7}, {%8,%9}, {%0,%1,%2,%3};"
        : "+f"(c[0]), "+f"(c[1]), "+f"(c[2]), "+f"(c[3])
        : "r"(a[0]), "r"(a[1]), "r"(a[2]), "r"(a[3]), "r"(b0), "r"(b1));
}

union UH2 { __half2 h; uint32_t u; };
__device__ __forceinline__ uint32_t pack_h2(float a, float b) {
    UH2 v; v.h = __floats2half2_rn(a, b);
    return v.u;
}
__device__ __forceinline__ int clamp_k(const int* kptr) {
    int kk = 2;
    if (kptr) { kk = *kptr; kk = kk < 1 ? 1 : (kk > MAXK ? MAXK : kk); }
    return kk;
}

// ---------------- routing kernels ----------------
__global__ void init_kernel() {
    if (threadIdx.x < NEXP) g_counts[threadIdx.x] = 0;
}

__global__ void router_kernel(const float* __restrict__ x,
                              const float* __restrict__ gW,
                              const float* __restrict__ gb,
                              const int* kptr, int T) {
    int gw = (blockIdx.x * blockDim.x + threadIdx.x) >> 5;
    int lane = threadIdx.x & 31;
    if (gw >= T) return;
    const float* xt = x + (size_t)gw * D_MODEL;
    float xr[32];
#pragma unroll
    for (int j = 0; j < 32; j++) xr[j] = xt[lane + j * 32];
    float lg[NEXP];
#pragma unroll
    for (int e = 0; e < NEXP; e++) {
        const float* w = gW + e * D_MODEL;
        float a = 0.f;
#pragma unroll
        for (int j = 0; j < 32; j++) a = fmaf(xr[j], w[lane + j * 32], a);
#pragma unroll
        for (int o = 16; o > 0; o >>= 1) a += __shfl_xor_sync(0xffffffffu, a, o);
        lg[e] = a + gb[e];
    }
    if (lane == 0) {
        int kk = clamp_k(kptr);
        float sc[MAXK]; int sel[MAXK];
        unsigned used = 0;
        for (int j = 0; j < kk; j++) {
            float bv = -3.0e38f; int bi = 0;
            for (int e = 0; e < NEXP; e++)
                if (!((used >> e) & 1u) && lg[e] > bv) { bv = lg[e]; bi = e; }
            used |= 1u << bi; sel[j] = bi; sc[j] = bv;
        }
        float m = sc[0], s = 0.f, p[MAXK];
        for (int j = 0; j < kk; j++) { p[j] = __expf(sc[j] - m); s += p[j]; }
        float inv = 1.f / s;
        for (int j = 0; j < kk; j++) {
            g_topidx[gw * MAXK + j] = sel[j];
            g_topw[gw * MAXK + j] = p[j] * inv;
            atomicAdd(&g_counts[sel[j]], 1);
        }
    }
}

__global__ void offsets_kernel() {
    if (threadIdx.x == 0 && blockIdx.x == 0) {
        int off = 0;
        for (int e = 0; e < NEXP; e++) { g_offsets[e] = off; off += g_counts[e]; g_cursor[e] = 0; }
    }
}

__global__ void assign_kernel(const int* kptr, int T) {
    int tid = blockIdx.x * blockDim.x + threadIdx.x;
    if (tid >= T * MAXK) return;
    int t = tid / MAXK, j = tid % MAXK;
    int kk = clamp_k(kptr);
    if (j >= kk) return;
    int e = g_topidx[t * MAXK + j];
    int r = atomicAdd(&g_cursor[e], 1);
    int slot = g_offsets[e] + r;
    g_slot2tok[slot] = t;
    g_slotw[slot] = g_topw[t * MAXK + j];
}

// ---------------- fused conversion kernel ----------------
// blocks [0, T*2):              x gather->fp16, 2 slots/block (128 thr each)
// [T*2, T*2+4096):              Wg fp32->fp16
// [T*2+4096, T*2+8192):         W1
// [T*2+8192, T*2+12288):        W2
// [T*2+12288, T*2+14336):       zero out
__global__ void conv_all_kernel(const float* __restrict__ x,
                                const float* __restrict__ Wg,
                                const float* __restrict__ W1,
                                const float* __restrict__ W2,
                                float* __restrict__ out,
                                int n4out, int T) {
    const int b = blockIdx.x;
    const int tid = threadIdx.x;
    const int NBX = T * 2;
    const int n8 = NEXP * D_FF * D_MODEL / 8;
    if (b < NBX) {
        int slot = b * 2 + (tid >> 7);
        int total = g_offsets[NEXP - 1] + g_counts[NEXP - 1];
        if (slot >= total) return;
        int tok = g_slot2tok[slot];
        int t = tid & 127;
        const float4* s = (const float4*)(x + (size_t)tok * D_MODEL) + t * 2;
        float4 a = s[0], bb = s[1];
        ((uint4*)(g_ahi + (size_t)slot * D_MODEL))[t] =
            make_uint4(pack_h2(a.x, a.y), pack_h2(a.z, a.w),
                       pack_h2(bb.x, bb.y), pack_h2(bb.z, bb.w));
    } else if (b < NBX + 12288) {
        int seg = (b - NBX) >> 12;            // 0=Wg 1=W1 2=W2
        int lb  = (b - NBX) & 4095;
        const float* src = seg == 0 ? Wg : seg == 1 ? W1 : W2;
        __half* dst = seg == 0 ? g_wghi : seg == 1 ? g_w1hi : g_w2hi;
        for (int i = lb * 256 + tid; i < n8; i += 4096 * 256) {
            const float4* s = (const float4*)src + (size_t)i * 2;
            float4 a = s[0], bb = s[1];
            ((uint4*)dst)[i] = make_uint4(pack_h2(a.x, a.y), pack_h2(a.z, a.w),
                                          pack_h2(bb.x, bb.y), pack_h2(bb.z, bb.w));
        }
    } else {
        int lb = b - (NBX + 12288);           // [0, 2048)
        for (int i = lb * 256 + tid; i < n4out; i += 2048 * 256)
            ((float4*)out)[i] = make_float4(0.f, 0.f, 0.f, 0.f);
    }
}

// ---------------- GEMM tiling ----------------
// smem row pitch = 80 bytes (32 fp16 + 8 pad), ldmatrix conflict-free (proven R6-R10)
// 4-stage pipeline, 20480 B/stage, 2 CTAs/SM.
#define G1_STAGE 20480
#define G2_STAGE 20480

// GEMM1 stage: A[128x32]@0, Bg[64x32]@10240, Bv[64x32]@15360
__device__ __forceinline__ void g1_load(
    uint32_t base, const __half* aHi, const __half* bg, const __half* bv,
    int k0, int tid) {
#pragma unroll
    for (int i = 0; i < 4; i++) {          // 1024 chunks of 16B
        int idx = tid + i * 256;
        if (idx < 512) {                   // A: 128 rows x 4
            int row = idx >> 2, c = idx & 3;
            cpasync16(base + row * 80 + c * 16,
                      aHi + (size_t)row * D_MODEL + k0 + c * 8);
        } else if (idx < 768) {            // Bg: 64 rows x 4
            int rem = idx - 512;
            int row = rem >> 2, c = rem & 3;
            cpasync16(base + 10240 + row * 80 + c * 16,
                      bg + (size_t)row * D_MODEL + k0 + c * 8);
        } else {                           // Bv
            int rem = idx - 768;
            int row = rem >> 2, c = rem & 3;
            cpasync16(base + 15360 + row * 80 + c * 16,
                      bv + (size_t)row * D_MODEL + k0 + c * 8);
        }
    }
}

// ---------------- GEMM1: G = X Wg^T, V = X W1^T, h = silu(G)*V ----------------
// 256 threads, BM=128, BN=64, warp grid 2M x 4N (16 cols/warp).
__global__ __launch_bounds__(256, 2) void gemm1_mma() {
    const int e = blockIdx.z;
    const int cnt = g_counts[e];
    const int m0 = blockIdx.x * 128;
    if (m0 >= cnt) return;
    const int n0 = blockIdx.y * 64;
    const int offs = g_offsets[e];
    extern __shared__ char smem[];
    uint32_t sb = s2u(smem);
    const int tid = threadIdx.x, lane = tid & 31, wid = tid >> 5;
    const int wM = wid >> 2, wN = wid & 3;

    const __half* aHi = g_ahi + (size_t)(offs + m0) * D_MODEL;
    const size_t wb = (size_t)e * D_FF * D_MODEL + (size_t)n0 * D_MODEL;
    const __half* bg = g_wghi + wb;
    const __half* bv = g_w1hi + wb;

    g1_load(sb + 0 * G1_STAGE, aHi, bg, bv, 0, tid);  CP_COMMIT();
    g1_load(sb + 1 * G1_STAGE, aHi, bg, bv, 32, tid); CP_COMMIT();
    g1_load(sb + 2 * G1_STAGE, aHi, bg, bv, 64, tid); CP_COMMIT();

    float accG[4][2][4] = {}, accV[4][2][4] = {};
    const int aRow = lane & 15, aK = (lane >> 4) << 3;
    const int bRow = (lane & 7) | ((lane >> 4) << 3);
    const int bK = ((lane >> 3) & 1) << 3;

    const int NCH = D_MODEL / 32;  // 32
    for (int j = 0; j < NCH; j++) {
        CP_WAIT2();
        __syncthreads();
        if (j + 3 < NCH)
            g1_load(sb + ((j + 3) & 3) * G1_STAGE, aHi, bg, bv, (j + 3) * 32, tid);
        CP_COMMIT();
        const uint32_t bA = sb + (j & 3) * G1_STAGE;
#pragma unroll
        for (int kk = 0; kk < 32; kk += 16) {
            uint32_t ah[4][4];
#pragma unroll
            for (int mt = 0; mt < 4; mt++) {
                uint32_t r = wM * 64 + mt * 16 + aRow;
                ldsm4(ah[mt], bA + r * 80 + (kk + aK) * 2);
            }
            uint32_t bgf[4], bvf[4];
            {
                uint32_t rN = wN * 16 + bRow;
                uint32_t cb2 = (kk + bK) * 2;
                ldsm4(bgf, bA + 10240 + rN * 80 + cb2);
                ldsm4(bvf, bA + 15360 + rN * 80 + cb2);
            }
#pragma unroll
            for (int mt = 0; mt < 4; mt++)
#pragma unroll
                for (int sub = 0; sub < 2; sub++) {
                    mma16816(accG[mt][sub], ah[mt], bgf[sub * 2], bgf[sub * 2 + 1]);
                    mma16816(accV[mt][sub], ah[mt], bvf[sub * 2], bvf[sub * 2 + 1]);
                }
        }
    }

#pragma unroll
    for (int mt = 0; mt < 4; mt++)
#pragma unroll
        for (int half_ = 0; half_ < 2; half_++) {
            int r = m0 + wM * 64 + mt * 16 + (lane >> 2) + half_ * 8;
            if (r < cnt) {
                size_t rowb = (size_t)(offs + r) * D_FF;
#pragma unroll
                for (int sub = 0; sub < 2; sub++) {
                    float gg0 = accG[mt][sub][half_ * 2 + 0];
                    float gg1 = accG[mt][sub][half_ * 2 + 1];
                    float vv0 = accV[mt][sub][half_ * 2 + 0];
                    float vv1 = accV[mt][sub][half_ * 2 + 1];
                    float h0 = gg0 / (1.f + __expf(-gg0)) * vv0;
                    float h1 = gg1 / (1.f + __expf(-gg1)) * vv1;
                    int col = n0 + wN * 16 + sub * 8 + (lane & 3) * 2;
                    *(uint32_t*)(g_hhi + rowb + col) = pack_h2(h0, h1);
                }
            }
        }
}

// GEMM2 stage: A[128x32]@0, B[128x32]@10240
__device__ __forceinline__ void g2_load(
    uint32_t base, const __half* aHi, const __half* bHi, int k0, int tid) {
#pragma unroll
    for (int i = 0; i < 4; i++) {          // 1024 chunks
        int idx = tid + i * 256;
        if (idx < 512) {                   // A: 128 rows x 4
            int row = idx >> 2, c = idx & 3;
            cpasync16(base + row * 80 + c * 16,
                      aHi + (size_t)row * D_FF + k0 + c * 8);
        } else {                           // B: 128 rows x 4
            int rem = idx - 512;
            int row = rem >> 2, c = rem & 3;
            cpasync16(base + 10240 + row * 80 + c * 16,
                      bHi + (size_t)row * D_FF + k0 + c * 8);
        }
    }
}

// ---------------- GEMM2: y = h W2^T, fused weighted scatter into out ----------------
// 256 threads, BM=128, BN=128, warp grid 2M x 4N (32 cols/warp).
__global__ __launch_bounds__(256, 2) void gemm2_mma(float* __restrict__ out) {
    const int e = blockIdx.z;
    const int cnt = g_counts[e];
    const int m0 = blockIdx.x * 128;
    if (m0 >= cnt) return;
    const int n0 = blockIdx.y * 128;
    const int offs = g_offsets[e];
    extern __shared__ char smem[];
    uint32_t sb = s2u(smem);
    const int tid = threadIdx.x, lane = tid & 31, wid = tid >> 5;
    const int wM = wid >> 2, wN = wid & 3;

    const __half* aHi = g_hhi + (size_t)(offs + m0) * D_FF;
    const __half* bHi = g_w2hi + (size_t)e * D_MODEL * D_FF + (size_t)n0 * D_FF;

    g2_load(sb + 0 * G2_STAGE, aHi, bHi, 0, tid);  CP_COMMIT();
    g2_load(sb + 1 * G2_STAGE, aHi, bHi, 32, tid); CP_COMMIT();
    g2_load(sb + 2 * G2_STAGE, aHi, bHi, 64, tid); CP_COMMIT();

    float acc[4][4][4] = {};
    const int aRow = lane & 15, aK = (lane >> 4) << 3;
    const int bRow = (lane & 7) | ((lane >> 4) << 3);
    const int bK = ((lane >> 3) & 1) << 3;

    const int NCH = D_FF / 32;  // 128
    for (int j = 0; j < NCH; j++) {
        CP_WAIT2();
        __syncthreads();
        if (j + 3 < NCH)
            g2_load(sb + ((j + 3) & 3) * G2_STAGE, aHi, bHi, (j + 3) * 32, tid);
        CP_COMMIT();
        const uint32_t bA = sb + (j & 3) * G2_STAGE;
#pragma unroll
        for (int kk = 0; kk < 32; kk += 16) {
            uint32_t ah[4][4];
#pragma unroll
            for (int mt = 0; mt < 4; mt++) {
                uint32_t r = wM * 64 + mt * 16 + aRow;
                ldsm4(ah[mt], bA + r * 80 + (kk + aK) * 2);
            }
#pragma unroll
            for (int np = 0; np < 2; np++) {
                uint32_t rB = wN * 32 + np * 16 + bRow;
                uint32_t bh[4];
                ldsm4(bh, bA + 10240 + rB * 80 + (kk + bK) * 2);
#pragma unroll
                for (int mt = 0; mt < 4; mt++)
#pragma unroll
                    for (int sub = 0; sub < 2; sub++)
                        mma16816(acc[mt][np * 2 + sub], ah[mt], bh[sub * 2], bh[sub * 2 + 1]);
            }
        }
    }

    // epilogue: out[tok] += w_slot * y_row (k contributions, fp add commutative for k<=2 order sets)
#pragma unroll
    for (int mt = 0; mt < 4; mt++)
#pragma unroll
        for (int half_ = 0; half_ < 2; half_++) {
            int r = m0 + wM * 64 + mt * 16 + (lane >> 2) + half_ * 8;
            if (r < cnt) {
                int tok = g_slot2tok[offs + r];
                float w = g_slotw[offs + r];
                float* orow = out + (size_t)tok * D_MODEL;
#pragma unroll
                for (int nt = 0; nt < 4; nt++) {
                    int col = n0 + wN * 32 + nt * 8 + (lane & 3) * 2;
                    atomicAdd(&orow[col],     w * acc[mt][nt][half_ * 2 + 0]);
                    atomicAdd(&orow[col + 1], w * acc[mt][nt][half_ * 2 + 1]);
                }
            }
        }
}

// ---------------- launch ----------------
extern "C" void kernel_launch(void* const* d_in, const int* in_sizes, int n_in,
                              void* d_out, int out_size) {
    const float* x  = (const float*)d_in[0];
    const float* gW = (const float*)d_in[1];
    const float* gb = (const float*)d_in[2];
    const float* Wg = (const float*)d_in[3];
    const float* W1 = (const float*)d_in[4];
    const float* W2 = (const float*)d_in[5];
    const int* kptr = (n_in > 6) ? (const int*)d_in[6] : nullptr;
    float* out = (float*)d_out;
    const int T = in_sizes[0] / D_MODEL;

    cudaFuncSetAttribute(gemm1_mma, cudaFuncAttributeMaxDynamicSharedMemorySize, 4 * G1_STAGE);
    cudaFuncSetAttribute(gemm2_mma, cudaFuncAttributeMaxDynamicSharedMemorySize, 4 * G2_STAGE);

    init_kernel<<<1, 32>>>();
    router_kernel<<<(T + 7) / 8, 256>>>(x, gW, gb, kptr, T);
    offsets_kernel<<<1, 1>>>();
    assign_kernel<<<(T * MAXK + 255) / 256, 256>>>(kptr, T);

    const int nconv = T * 2 + 12288 + 2048;
    conv_all_kernel<<<nconv, 256>>>(x, Wg, W1, W2, out, out_size / 4, T);

    // grid x sized for worst plausible expert imbalance (cnt up to 4096 = ~48 sigma)
    gemm1_mma<<<dim3(32, D_FF / 64, NEXP), 256, 4 * G1_STAGE>>>();
    gemm2_mma<<<dim3(32, D_MODEL / 128, NEXP), 256, 4 * G2_STAGE>>>(out);
}

// round 13
// speedup vs baseline: 6.4049x; 1.1006x over previous
#include <cuda_runtime.h>
#include <cuda_bf16.h>
#include <cuda_fp16.h>
#include <math.h>
#include <stdint.h>

#define D_MODEL 1024
#define D_FF    4096
#define NEXP    8
#define MAXK    4
#define MAXT    8192
#define MAXSLOTS (MAXT*MAXK)
#define PADS     (MAXSLOTS+256)

typedef unsigned long long ull;

// ---------------- static device scratch ----------------
__device__ int   g_counts[NEXP];
__device__ int   g_cursor[NEXP];
__device__ int   g_offsets[NEXP];
__device__ int   g_slot2tok[MAXSLOTS];
__device__ float g_slotw[MAXSLOTS];
__device__ float g_topw[MAXSLOTS];
__device__ int   g_topidx[MAXSLOTS];

__device__ __align__(256) __half g_wghi[(size_t)NEXP*D_FF*D_MODEL];
__device__ __align__(256) __half g_w1hi[(size_t)NEXP*D_FF*D_MODEL];
__device__ __align__(256) __half g_w2hi[(size_t)NEXP*D_MODEL*D_FF];
__device__ __align__(256) __half g_ahi[(size_t)PADS*D_MODEL];
__device__ __align__(256) __half g_hhi[(size_t)PADS*D_FF];

// ---------------- helpers ----------------
__device__ __forceinline__ uint32_t s2u(const void* p) {
    uint32_t a;
    asm("{ .reg .u64 t; cvta.to.shared.u64 t, %1; cvt.u32.u64 %0, t; }"
        : "=r"(a) : "l"(p));
    return a;
}
__device__ __forceinline__ void cpasync16(uint32_t dst, const void* src) {
    asm volatile("cp.async.cg.shared.global [%0], [%1], 16;" :: "r"(dst), "l"(src) : "memory");
}
#define CP_COMMIT() asm volatile("cp.async.commit_group;" ::: "memory")
#define CP_WAIT1()  asm volatile("cp.async.wait_group 1;" ::: "memory")

__device__ __forceinline__ void ldsm4(uint32_t (&r)[4], uint32_t addr) {
    asm volatile("ldmatrix.sync.aligned.m8n8.x4.shared.b16 {%0,%1,%2,%3}, [%4];"
                 : "=r"(r[0]), "=r"(r[1]), "=r"(r[2]), "=r"(r[3]) : "r"(addr));
}
__device__ __forceinline__ void mma16816(float (&c)[4], const uint32_t (&a)[4],
                                         uint32_t b0, uint32_t b1) {
    asm volatile(
        "mma.sync.aligned.m16n8k16.row.col.f32.f16.f16.f32 "
        "{%0,%1,%2,%3}, {%4,%5,%6,%7}, {%8,%9}, {%0,%1,%2,%3};"
        : "+f"(c[0]), "+f"(c[1]), "+f"(c[2]), "+f"(c[3])
        : "r"(a[0]), "r"(a[1]), "r"(a[2]), "r"(a[3]), "r"(b0), "r"(b1));
}

union UH2 { __half2 h; uint32_t u; };
__device__ __forceinline__ uint32_t pack_h2(float a, float b) {
    UH2 v; v.h = __floats2half2_rn(a, b);
    return v.u;
}
__device__ __forceinline__ int clamp_k(const int* kptr) {
    int kk = 2;
    if (kptr) { kk = *kptr; kk = kk < 1 ? 1 : (kk > MAXK ? MAXK : kk); }
    return kk;
}

// ---------------- routing kernels ----------------
__global__ void init_kernel() {
    if (threadIdx.x < NEXP) { g_counts[threadIdx.x] = 0; g_cursor[threadIdx.x] = 0; }
}

__global__ void router_kernel(const float* __restrict__ x,
                              const float* __restrict__ gW,
                              const float* __restrict__ gb,
                              const int* kptr, int T) {
    int gw = (blockIdx.x * blockDim.x + threadIdx.x) >> 5;
    int lane = threadIdx.x & 31;
    if (gw >= T) return;
    const float* xt = x + (size_t)gw * D_MODEL;
    float xr[32];
#pragma unroll
    for (int j = 0; j < 32; j++) xr[j] = xt[lane + j * 32];
    float lg[NEXP];
#pragma unroll
    for (int e = 0; e < NEXP; e++) {
        const float* w = gW + e * D_MODEL;
        float a = 0.f;
#pragma unroll
        for (int j = 0; j < 32; j++) a = fmaf(xr[j], w[lane + j * 32], a);
#pragma unroll
        for (int o = 16; o > 0; o >>= 1) a += __shfl_xor_sync(0xffffffffu, a, o);
        lg[e] = a + gb[e];
    }
    if (lane == 0) {
        int kk = clamp_k(kptr);
        float sc[MAXK]; int sel[MAXK];
        unsigned used = 0;
        for (int j = 0; j < kk; j++) {
            float bv = -3.0e38f; int bi = 0;
            for (int e = 0; e < NEXP; e++)
                if (!((used >> e) & 1u) && lg[e] > bv) { bv = lg[e]; bi = e; }
            used |= 1u << bi; sel[j] = bi; sc[j] = bv;
        }
        float m = sc[0], s = 0.f, p[MAXK];
        for (int j = 0; j < kk; j++) { p[j] = __expf(sc[j] - m); s += p[j]; }
        float inv = 1.f / s;
        for (int j = 0; j < kk; j++) {
            g_topidx[gw * MAXK + j] = sel[j];
            g_topw[gw * MAXK + j] = p[j] * inv;
            atomicAdd(&g_counts[sel[j]], 1);
        }
    }
}

// assign with inline prefix-scan (8 experts); block 0 publishes g_offsets.
__global__ void assign_kernel(const int* kptr, int T) {
    if (blockIdx.x == 0 && threadIdx.x < NEXP) {
        int off = 0;
        for (int ee = 0; ee < (int)threadIdx.x; ee++) off += g_counts[ee];
        g_offsets[threadIdx.x] = off;
    }
    int tid = blockIdx.x * blockDim.x + threadIdx.x;
    if (tid >= T * MAXK) return;
    int t = tid / MAXK, j = tid % MAXK;
    int kk = clamp_k(kptr);
    if (j >= kk) return;
    int e = g_topidx[t * MAXK + j];
    int off = 0;
    for (int ee = 0; ee < e; ee++) off += g_counts[ee];
    int r = atomicAdd(&g_cursor[e], 1);
    int slot = off + r;
    g_slot2tok[slot] = t;
    g_slotw[slot] = g_topw[t * MAXK + j];
}

// ---------------- fused conversion kernel ----------------
__global__ void conv_all_kernel(const float* __restrict__ x,
                                const float* __restrict__ Wg,
                                const float* __restrict__ W1,
                                const float* __restrict__ W2,
                                float* __restrict__ out,
                                int n4out, int T) {
    const int b = blockIdx.x;
    const int tid = threadIdx.x;
    const int NBX = T * 2;
    const int n8 = NEXP * D_FF * D_MODEL / 8;
    if (b < NBX) {
        int slot = b * 2 + (tid >> 7);
        int total = g_offsets[NEXP - 1] + g_counts[NEXP - 1];
        if (slot >= total) return;
        int tok = g_slot2tok[slot];
        int t = tid & 127;
        const float4* s = (const float4*)(x + (size_t)tok * D_MODEL) + t * 2;
        float4 a = s[0], bb = s[1];
        ((uint4*)(g_ahi + (size_t)slot * D_MODEL))[t] =
            make_uint4(pack_h2(a.x, a.y), pack_h2(a.z, a.w),
                       pack_h2(bb.x, bb.y), pack_h2(bb.z, bb.w));
    } else if (b < NBX + 12288) {
        int seg = (b - NBX) >> 12;            // 0=Wg 1=W1 2=W2
        int lb  = (b - NBX) & 4095;
        const float* src = seg == 0 ? Wg : seg == 1 ? W1 : W2;
        __half* dst = seg == 0 ? g_wghi : seg == 1 ? g_w1hi : g_w2hi;
        for (int i = lb * 256 + tid; i < n8; i += 4096 * 256) {
            const float4* s = (const float4*)src + (size_t)i * 2;
            float4 a = s[0], bb = s[1];
            ((uint4*)dst)[i] = make_uint4(pack_h2(a.x, a.y), pack_h2(a.z, a.w),
                                          pack_h2(bb.x, bb.y), pack_h2(bb.z, bb.w));
        }
    } else {
        int lb = b - (NBX + 12288);           // [0, 2048)
        for (int i = lb * 256 + tid; i < n4out; i += 2048 * 256)
            ((float4*)out)[i] = make_float4(0.f, 0.f, 0.f, 0.f);
    }
}

// ---------------- GEMM tiling ----------------
// 64-k chunks, row pitch 144 B (128 data + 16 pad; (144/4)%32=4 -> 8-row ldmatrix
// group hits banks {0,4,..,28} full-cycle: conflict-free). 3-stage, 2 CTAs/SM.
#define PITCH   144
#define G_STAGE 36864   // GEMM1: A 128*144 + Bg 64*144 + Bv 64*144 ; GEMM2: A 128*144 + B 128*144

// GEMM1 stage: A[128x64]@0, Bg[64x64]@18432, Bv[64x64]@27648
__device__ __forceinline__ void g1_load(
    uint32_t base, const __half* aHi, const __half* bg, const __half* bv,
    int k0, int tid) {
#pragma unroll
    for (int i = 0; i < 8; i++) {          // 2048 chunks of 16B
        int idx = tid + i * 256;
        if (idx < 1024) {                  // A: 128 rows x 8
            int row = idx >> 3, c = idx & 7;
            cpasync16(base + row * PITCH + c * 16,
                      aHi + (size_t)row * D_MODEL + k0 + c * 8);
        } else if (idx < 1536) {           // Bg: 64 rows x 8
            int rem = idx - 1024;
            int row = rem >> 3, c = rem & 7;
            cpasync16(base + 18432 + row * PITCH + c * 16,
                      bg + (size_t)row * D_MODEL + k0 + c * 8);
        } else {                           // Bv
            int rem = idx - 1536;
            int row = rem >> 3, c = rem & 7;
            cpasync16(base + 27648 + row * PITCH + c * 16,
                      bv + (size_t)row * D_MODEL + k0 + c * 8);
        }
    }
}

// ---------------- GEMM1: G = X Wg^T, V = X W1^T, h = silu(G)*V ----------------
// 256 threads, BM=128, BN=64, warp grid 2M x 4N.
__global__ __launch_bounds__(256, 2) void gemm1_mma() {
    const int e = blockIdx.z;
    const int cnt = g_counts[e];
    const int m0 = blockIdx.x * 128;
    if (m0 >= cnt) return;
    const int n0 = blockIdx.y * 64;
    const int offs = g_offsets[e];
    extern __shared__ char smem[];
    uint32_t sb = s2u(smem);
    const int tid = threadIdx.x, lane = tid & 31, wid = tid >> 5;
    const int wM = wid >> 2, wN = wid & 3;

    const __half* aHi = g_ahi + (size_t)(offs + m0) * D_MODEL;
    const size_t wb = (size_t)e * D_FF * D_MODEL + (size_t)n0 * D_MODEL;
    const __half* bg = g_wghi + wb;
    const __half* bv = g_w1hi + wb;

    g1_load(sb + 0 * G_STAGE, aHi, bg, bv, 0, tid);  CP_COMMIT();
    g1_load(sb + 1 * G_STAGE, aHi, bg, bv, 64, tid); CP_COMMIT();

    float accG[4][2][4] = {}, accV[4][2][4] = {};
    const int aRow = lane & 15, aK = (lane >> 4) << 3;
    const int bRow = (lane & 7) | ((lane >> 4) << 3);
    const int bK = ((lane >> 3) & 1) << 3;

    const int NCH = D_MODEL / 64;  // 16
    int sj = 0, sp = 2;
    for (int j = 0; j < NCH; j++) {
        CP_WAIT1();
        __syncthreads();
        if (j + 2 < NCH) {
            g1_load(sb + sp * G_STAGE, aHi, bg, bv, (j + 2) * 64, tid);
            sp = sp == 2 ? 0 : sp + 1;
        }
        CP_COMMIT();
        const uint32_t bA = sb + sj * G_STAGE;
        sj = sj == 2 ? 0 : sj + 1;
#pragma unroll
        for (int kk = 0; kk < 64; kk += 16) {
            uint32_t ah[4][4];
#pragma unroll
            for (int mt = 0; mt < 4; mt++) {
                uint32_t r = wM * 64 + mt * 16 + aRow;
                ldsm4(ah[mt], bA + r * PITCH + (kk + aK) * 2);
            }
            uint32_t bgf[4], bvf[4];
            {
                uint32_t rN = wN * 16 + bRow;
                uint32_t cb2 = (kk + bK) * 2;
                ldsm4(bgf, bA + 18432 + rN * PITCH + cb2);
                ldsm4(bvf, bA + 27648 + rN * PITCH + cb2);
            }
#pragma unroll
            for (int mt = 0; mt < 4; mt++)
#pragma unroll
                for (int sub = 0; sub < 2; sub++) {
                    mma16816(accG[mt][sub], ah[mt], bgf[sub * 2], bgf[sub * 2 + 1]);
                    mma16816(accV[mt][sub], ah[mt], bvf[sub * 2], bvf[sub * 2 + 1]);
                }
        }
    }

#pragma unroll
    for (int mt = 0; mt < 4; mt++)
#pragma unroll
        for (int half_ = 0; half_ < 2; half_++) {
            int r = m0 + wM * 64 + mt * 16 + (lane >> 2) + half_ * 8;
            if (r < cnt) {
                size_t rowb = (size_t)(offs + r) * D_FF;
#pragma unroll
                for (int sub = 0; sub < 2; sub++) {
                    float gg0 = accG[mt][sub][half_ * 2 + 0];
                    float gg1 = accG[mt][sub][half_ * 2 + 1];
                    float vv0 = accV[mt][sub][half_ * 2 + 0];
                    float vv1 = accV[mt][sub][half_ * 2 + 1];
                    float h0 = gg0 / (1.f + __expf(-gg0)) * vv0;
                    float h1 = gg1 / (1.f + __expf(-gg1)) * vv1;
                    int col = n0 + wN * 16 + sub * 8 + (lane & 3) * 2;
                    *(uint32_t*)(g_hhi + rowb + col) = pack_h2(h0, h1);
                }
            }
        }
}

// GEMM2 stage: A[128x64]@0, B[128x64]@18432
__device__ __forceinline__ void g2_load(
    uint32_t base, const __half* aHi, const __half* bHi, int k0, int tid) {
#pragma unroll
    for (int i = 0; i < 8; i++) {          // 2048 chunks
        int idx = tid + i * 256;
        if (idx < 1024) {                  // A: 128 rows x 8
            int row = idx >> 3, c = idx & 7;
            cpasync16(base + row * PITCH + c * 16,
                      aHi + (size_t)row * D_FF + k0 + c * 8);
        } else {                           // B: 128 rows x 8
            int rem = idx - 1024;
            int row = rem >> 3, c = rem & 7;
            cpasync16(base + 18432 + row * PITCH + c * 16,
                      bHi + (size_t)row * D_FF + k0 + c * 8);
        }
    }
}

// ---------------- GEMM2: y = h W2^T, fused weighted scatter into out ----------------
// 256 threads, BM=128, BN=128, warp grid 2M x 4N.
__global__ __launch_bounds__(256, 2) void gemm2_mma(float* __restrict__ out) {
    const int e = blockIdx.z;
    const int cnt = g_counts[e];
    const int m0 = blockIdx.x * 128;
    if (m0 >= cnt) return;
    const int n0 = blockIdx.y * 128;
    const int offs = g_offsets[e];
    extern __shared__ char smem[];
    uint32_t sb = s2u(smem);
    const int tid = threadIdx.x, lane = tid & 31, wid = tid >> 5;
    const int wM = wid >> 2, wN = wid & 3;

    const __half* aHi = g_hhi + (size_t)(offs + m0) * D_FF;
    const __half* bHi = g_w2hi + (size_t)e * D_MODEL * D_FF + (size_t)n0 * D_FF;

    g2_load(sb + 0 * G_STAGE, aHi, bHi, 0, tid);  CP_COMMIT();
    g2_load(sb + 1 * G_STAGE, aHi, bHi, 64, tid); CP_COMMIT();

    float acc[4][4][4] = {};
    const int aRow = lane & 15, aK = (lane >> 4) << 3;
    const int bRow = (lane & 7) | ((lane >> 4) << 3);
    const int bK = ((lane >> 3) & 1) << 3;

    const int NCH = D_FF / 64;  // 64
    int sj = 0, sp = 2;
    for (int j = 0; j < NCH; j++) {
        CP_WAIT1();
        __syncthreads();
        if (j + 2 < NCH) {
            g2_load(sb + sp * G_STAGE, aHi, bHi, (j + 2) * 64, tid);
            sp = sp == 2 ? 0 : sp + 1;
        }
        CP_COMMIT();
        const uint32_t bA = sb + sj * G_STAGE;
        sj = sj == 2 ? 0 : sj + 1;
#pragma unroll
        for (int kk = 0; kk < 64; kk += 16) {
            uint32_t ah[4][4];
#pragma unroll
            for (int mt = 0; mt < 4; mt++) {
                uint32_t r = wM * 64 + mt * 16 + aRow;
                ldsm4(ah[mt], bA + r * PITCH + (kk + aK) * 2);
            }
#pragma unroll
            for (int np = 0; np < 2; np++) {
                uint32_t rB = wN * 32 + np * 16 + bRow;
                uint32_t bh[4];
                ldsm4(bh, bA + 18432 + rB * PITCH + (kk + bK) * 2);
#pragma unroll
                for (int mt = 0; mt < 4; mt++)
#pragma unroll
                    for (int sub = 0; sub < 2; sub++)
                        mma16816(acc[mt][np * 2 + sub], ah[mt], bh[sub * 2], bh[sub * 2 + 1]);
            }
        }
    }

    // epilogue: out[tok] += w_slot * y_row (k=2 contributions: deterministic sum)
#pragma unroll
    for (int mt = 0; mt < 4; mt++)
#pragma unroll
        for (int half_ = 0; half_ < 2; half_++) {
            int r = m0 + wM * 64 + mt * 16 + (lane >> 2) + half_ * 8;
            if (r < cnt) {
                int tok = g_slot2tok[offs + r];
                float w = g_slotw[offs + r];
                float* orow = out + (size_t)tok * D_MODEL;
#pragma unroll
                for (int nt = 0; nt < 4; nt++) {
                    int col = n0 + wN * 32 + nt * 8 + (lane & 3) * 2;
                    atomicAdd(&orow[col],     w * acc[mt][nt][half_ * 2 + 0]);
                    atomicAdd(&orow[col + 1], w * acc[mt][nt][half_ * 2 + 1]);
                }
            }
        }
}

// ---------------- launch ----------------
extern "C" void kernel_launch(void* const* d_in, const int* in_sizes, int n_in,
                              void* d_out, int out_size) {
    const float* x  = (const float*)d_in[0];
    const float* gW = (const float*)d_in[1];
    const float* gb = (const float*)d_in[2];
    const float* Wg = (const float*)d_in[3];
    const float* W1 = (const float*)d_in[4];
    const float* W2 = (const float*)d_in[5];
    const int* kptr = (n_in > 6) ? (const int*)d_in[6] : nullptr;
    float* out = (float*)d_out;
    const int T = in_sizes[0] / D_MODEL;

    cudaFuncSetAttribute(gemm1_mma, cudaFuncAttributeMaxDynamicSharedMemorySize, 3 * G_STAGE);
    cudaFuncSetAttribute(gemm2_mma, cudaFuncAttributeMaxDynamicSharedMemorySize, 3 * G_STAGE);

    init_kernel<<<1, 32>>>();
    router_kernel<<<(T + 7) / 8, 256>>>(x, gW, gb, kptr, T);
    assign_kernel<<<(T * MAXK + 255) / 256, 256>>>(kptr, T);

    const int nconv = T * 2 + 12288 + 2048;
    conv_all_kernel<<<nconv, 256>>>(x, Wg, W1, W2, out, out_size / 4, T);

    gemm1_mma<<<dim3(32, D_FF / 64, NEXP), 256, 3 * G_STAGE>>>();
    gemm2_mma<<<dim3(32, D_MODEL / 128, NEXP), 256, 3 * G_STAGE>>>(out);
}